// round 1
// baseline (speedup 1.0000x reference)
#include <cuda_runtime.h>
#include <math.h>

#define F_ 2
#define V_ 4
#define FV 8
#define E_ 2048
#define NI 512
#define NO 512
#define M_ 514
#define GMIN 0.01f
#define GMAX 10.0f
#define PGMIN 1e-4f

// ---------------- scratch (static device globals; no allocation) -------------
__device__ float d_Weff[FV * M_ * NO];     // theta_noisy / denom
__device__ float d_Hm[FV * M_ * NO];       // g_tilde * sign(theta_noisy)
__device__ float d_gtilde[M_ * NO];
__device__ float d_G[NO];                  // sum_m g_tilde[m,n]
__device__ float d_gsumm[M_];              // sum_n g_tilde[m,n]
__device__ float d_denp[FV * 8 * NO];      // partial |theta_noisy| sums over m-chunks
__device__ float4 d_actp[NO];              // chosen pTanh params per column
__device__ float d_p1p[FV * 16];           // p1 partials
__device__ float d_pwp[16 * 8 * FV];       // gemm-block power partials (p2+p3)

__constant__ float c_etas[16] = {
    0.05f, 0.90f, 0.20f, 8.0f,
    0.10f, 0.80f, 0.30f, 5.0f,
    0.00f, 1.00f, 0.25f, 10.0f,
    0.15f, 0.70f, 0.15f, 6.0f};

__device__ __forceinline__ float th_clip(float t) {
    return fminf(fmaxf(t, -GMAX), GMAX);
}
__device__ __forceinline__ float th_fwd(float t) {
    float c = th_clip(t);
    return (fabsf(c) < GMIN) ? 0.0f : c;
}

// packed fp32x2 FMA helpers (sm_103a)
__device__ __forceinline__ void fma2(unsigned long long& d, unsigned long long a,
                                     unsigned long long b) {
    asm("fma.rn.f32x2 %0, %1, %2, %0;" : "+l"(d) : "l"(a), "l"(b));
}
__device__ __forceinline__ float2 unpack2(unsigned long long v) {
    float2 r;
    asm("mov.b64 {%0,%1}, %2;" : "=f"(r.x), "=f"(r.y) : "l"(v));
    return r;
}

// ---------------- g_tilde, G ------------------------------------------------
__global__ void k_gtilde(const float* __restrict__ theta) {
    int n = blockIdx.x;
    int t = threadIdx.x;
    __shared__ float red[128];
    float mn = 1e30f;
    for (int m = t; m < M_; m += 128)
        mn = fminf(mn, fabsf(th_clip(theta[m * NO + n])));
    red[t] = mn;
    __syncthreads();
    for (int s = 64; s > 0; s >>= 1) {
        if (t < s) red[t] = fminf(red[t], red[t + s]);
        __syncthreads();
    }
    float scale = PGMIN / red[0];
    __syncthreads();
    float sum = 0.f;
    for (int m = t; m < M_; m += 128) {
        float g = fabsf(th_clip(theta[m * NO + n])) * scale;
        d_gtilde[m * NO + n] = g;
        sum += g;
    }
    red[t] = sum;
    __syncthreads();
    for (int s = 64; s > 0; s >>= 1) {
        if (t < s) red[t] += red[t + s];
        __syncthreads();
    }
    if (t == 0) d_G[n] = red[0];
}

// ---------------- gsum_m ----------------------------------------------------
__global__ void k_gsumm() {
    int m = blockIdx.x;
    int t = threadIdx.x;
    __shared__ float red[128];
    float s = 0.f;
    for (int n = t; n < NO; n += 128) s += d_gtilde[m * NO + n];
    red[t] = s;
    __syncthreads();
    for (int k = 64; k > 0; k >>= 1) {
        if (t < k) red[t] += red[t + k];
        __syncthreads();
    }
    if (t == 0) d_gsumm[m] = red[0];
}

// ---------------- activation select -----------------------------------------
__global__ void k_act(const float* __restrict__ coef, const float* __restrict__ gum) {
    int n = blockIdx.x * blockDim.x + threadIdx.x;
    if (n >= NO) return;
    float best = -1e30f;
    int bi = 0;
#pragma unroll
    for (int i = 0; i < 4; i++) {
        float c = fminf(fmaxf(coef[i * NO + n], -1.f), 1.f);
        float g = gum[i * NO + n];
        float gn = -logf(-logf(g + 1e-20f) + 1e-20f);
        float v = c + gn;
        if (v > best) { best = v; bi = i; }
    }
    d_actp[n] = make_float4(c_etas[bi * 4 + 0], c_etas[bi * 4 + 1],
                            c_etas[bi * 4 + 2], c_etas[bi * 4 + 3]);
}

// ---------------- denom partials over m-chunks --------------------------------
__global__ void k_denp(const float* __restrict__ theta, const float* __restrict__ nu) {
    int n = threadIdx.x;            // 512 threads
    int c = blockIdx.x;             // 8 chunks
    int fv = blockIdx.y;            // 8
    int m0 = c * 65, m1 = min(M_, m0 + 65);
    float acc = 0.f;
    for (int m = m0; m < m1; m++) {
        float t = th_fwd(theta[m * NO + n]);
        float u = nu[((size_t)fv * M_ + m) * NO + n];
        acc += fabsf(t * (u * 0.2f + 0.9f));
    }
    d_denp[((size_t)fv * 8 + c) * NO + n] = acc;
}

// ---------------- fill Weff, H ------------------------------------------------
__global__ void k_wfill(const float* __restrict__ theta, const float* __restrict__ nu) {
    int n = threadIdx.x;
    int c = blockIdx.x;
    int fv = blockIdx.y;
    float den = 1e-10f;
#pragma unroll
    for (int i = 0; i < 8; i++) den += d_denp[((size_t)fv * 8 + i) * NO + n];
    float inv = 1.f / den;
    int m0 = c * 65, m1 = min(M_, m0 + 65);
    for (int m = m0; m < m1; m++) {
        float t = th_fwd(theta[m * NO + n]);
        float u = nu[((size_t)fv * M_ + m) * NO + n];
        float tn = t * (u * 0.2f + 0.9f);
        size_t idx = ((size_t)fv * M_ + m) * NO + n;
        d_Weff[idx] = tn * inv;
        float s = (tn >= 0.f) ? 1.f : -1.f;
        d_Hm[idx] = d_gtilde[m * NO + n] * s;
    }
}

// ---------------- p1 partials: sum a^2 * gsum_m -------------------------------
__global__ void k_p1(const float* __restrict__ a) {
    __shared__ float gs[NI];
    __shared__ float red[256];
    int t = threadIdx.x;
    for (int i = t; i < NI; i += 256) gs[i] = d_gsumm[i];
    __syncthreads();
    int fv = blockIdx.y, ec = blockIdx.x;
    const float* base = a + ((size_t)fv * E_ + ec * 128) * NI;
    float acc = 0.f;
    for (int e = 0; e < 128; e++) {
        const float* row = base + (size_t)e * NI;
        for (int m = t; m < NI; m += 256) {
            float x = row[m];
            acc += x * x * gs[m];
        }
    }
    red[t] = acc;
    __syncthreads();
    for (int s = 128; s > 0; s >>= 1) {
        if (t < s) red[t] += red[t + s];
        __syncthreads();
    }
    if (t == 0) d_p1p[fv * 16 + ec] = red[0];
}

// ---------------- main fused GEMM: Z = X@Weff, U = X@H, activation + power ----
#define BM 128
#define BN 64
#define BK 8

__global__ void __launch_bounds__(256, 2)
k_gemm(const float* __restrict__ a, float* __restrict__ out) {
    __shared__ __align__(16) float As[BK][BM];
    __shared__ __align__(16) float2 Bw[BK][BN];  // lane-duplicated
    __shared__ __align__(16) float2 Bh[BK][BN];

    int t = threadIdx.x;
    int fv = blockIdx.z;
    int e0 = blockIdx.x * BM;
    int n0 = blockIdx.y * BN;
    int tx = t & 15;   // 16 -> BN/TN(4)
    int ty = t >> 4;   // 16 -> BM/TM(8)

    // A loader: thread -> (row, 4 cols)
    int arow = t >> 1;
    int acol = (t & 1) * 4;
    const float* abase = a + ((size_t)fv * E_ + e0 + arow) * NI;
    // B loader: thread -> (2 rows, 1 col)
    int bn = t & 63;
    int br = t >> 6;

    unsigned long long accz[4][4], accu[4][4];
#pragma unroll
    for (int i = 0; i < 4; i++)
#pragma unroll
        for (int j = 0; j < 4; j++) { accz[i][j] = 0ull; accu[i][j] = 0ull; }

    for (int kt = 0; kt < 65; kt++) {
        int k0 = kt * BK;
        float4 av4;
        if (k0 < 512) {
            av4 = *(const float4*)(abase + k0 + acol);
        } else {  // k0 == 512: x_ext = [.., 1, 0, pad...]
            av4.x = (acol == 0) ? 1.0f : 0.0f;
            av4.y = 0.0f; av4.z = 0.0f; av4.w = 0.0f;
        }
        As[acol + 0][arow] = av4.x;
        As[acol + 1][arow] = av4.y;
        As[acol + 2][arow] = av4.z;
        As[acol + 3][arow] = av4.w;
#pragma unroll
        for (int rr = 0; rr < 2; rr++) {
            int r = br + rr * 4;
            int m = k0 + r;
            float w = 0.f, h = 0.f;
            if (m < M_) {
                size_t idx = ((size_t)fv * M_ + m) * NO + n0 + bn;
                w = d_Weff[idx];
                h = d_Hm[idx];
            }
            Bw[r][bn] = make_float2(w, w);
            Bh[r][bn] = make_float2(h, h);
        }
        __syncthreads();
#pragma unroll
        for (int kk = 0; kk < BK; kk++) {
            const ulonglong2* ap = (const ulonglong2*)&As[kk][ty * 8];
            ulonglong2 a01 = ap[0], a23 = ap[1];
            const ulonglong2* bwp = (const ulonglong2*)&Bw[kk][tx * 4];
            ulonglong2 bw01 = bwp[0], bw23 = bwp[1];
            const ulonglong2* bhp = (const ulonglong2*)&Bh[kk][tx * 4];
            ulonglong2 bh01 = bhp[0], bh23 = bhp[1];
            unsigned long long aa[4] = {a01.x, a01.y, a23.x, a23.y};
            unsigned long long bw_[4] = {bw01.x, bw01.y, bw23.x, bw23.y};
            unsigned long long bh_[4] = {bh01.x, bh01.y, bh23.x, bh23.y};
#pragma unroll
            for (int i = 0; i < 4; i++)
#pragma unroll
                for (int j = 0; j < 4; j++) {
                    fma2(accz[i][j], aa[i], bw_[j]);
                    fma2(accu[i][j], aa[i], bh_[j]);
                }
        }
        __syncthreads();
    }

    // epilogue
    int n_base = n0 + tx * 4;
    int e_base = e0 + ty * 8;
    float4 gv = *(const float4*)&d_G[n_base];
    float G_[4] = {gv.x, gv.y, gv.z, gv.w};
    float4 P[4];
#pragma unroll
    for (int j = 0; j < 4; j++) P[j] = d_actp[n_base + j];

    float pw = 0.f;
#pragma unroll
    for (int ip = 0; ip < 4; ip++) {
        float2 z[4], u[4];
#pragma unroll
        for (int j = 0; j < 4; j++) {
            z[j] = unpack2(accz[ip][j]);
            u[j] = unpack2(accu[ip][j]);
            pw += z[j].x * (z[j].x * G_[j] - 2.f * u[j].x);
            pw += z[j].y * (z[j].y * G_[j] - 2.f * u[j].y);
        }
        float4 o0, o1;
        o0.x = P[0].x + P[0].y * tanhf((z[0].x - P[0].z) * P[0].w);
        o0.y = P[1].x + P[1].y * tanhf((z[1].x - P[1].z) * P[1].w);
        o0.z = P[2].x + P[2].y * tanhf((z[2].x - P[2].z) * P[2].w);
        o0.w = P[3].x + P[3].y * tanhf((z[3].x - P[3].z) * P[3].w);
        o1.x = P[0].x + P[0].y * tanhf((z[0].y - P[0].z) * P[0].w);
        o1.y = P[1].x + P[1].y * tanhf((z[1].y - P[1].z) * P[1].w);
        o1.z = P[2].x + P[2].y * tanhf((z[2].y - P[2].z) * P[2].w);
        o1.w = P[3].x + P[3].y * tanhf((z[3].y - P[3].z) * P[3].w);
        size_t r0 = ((size_t)fv * E_ + e_base + 2 * ip) * NO + n_base;
        *(float4*)&out[r0] = o0;
        *(float4*)&out[r0 + NO] = o1;
    }

    __shared__ float red[256];
    red[t] = pw;
    __syncthreads();
    for (int s = 128; s > 0; s >>= 1) {
        if (t < s) red[t] += red[t + s];
        __syncthreads();
    }
    if (t == 0)
        d_pwp[(blockIdx.z * 8 + blockIdx.y) * 16 + blockIdx.x] = red[0];
}

// ---------------- final: assemble mac_power ----------------------------------
__global__ void k_final(float* __restrict__ out, int out_size) {
    __shared__ float red[256];
    int t = threadIdx.x;
    float s = 0.f;
    for (int i = t; i < 16 * 8 * FV; i += 256) s += d_pwp[i];
    for (int i = t; i < FV * 16; i += 256) s += d_p1p[i];
    red[t] = s;
    __syncthreads();
    for (int k = 128; k > 0; k >>= 1) {
        if (t < k) red[t] += red[t + k];
        __syncthreads();
    }
    if (t == 0) {
        // p1 contribution of the ones-column (m = 512): sx2 = E_ per (f,v)
        float p1_ones = (float)(FV * E_) * d_gsumm[512];
        float power = (red[0] + p1_ones) / (float)(E_ * V_ * F_);
        long long total = (long long)FV * E_ * NO;
        if (out_size > total) out[total] = power;
    }
}

extern "C" void kernel_launch(void* const* d_in, const int* in_sizes, int n_in,
                              void* d_out, int out_size) {
    const float* a     = (const float*)d_in[0];  // a_previous [F,V,E,NI]
    const float* theta = (const float*)d_in[1];  // theta_ [M,NO]
    const float* coef  = (const float*)d_in[2];  // cofficients_act [4,NO]
    const float* nu    = (const float*)d_in[3];  // noise_u [F,V,M,NO]
    const float* gum   = (const float*)d_in[4];  // gumbel_u [4,NO]
    float* out = (float*)d_out;
    (void)in_sizes; (void)n_in;

    k_gtilde<<<NO, 128>>>(theta);
    k_gsumm<<<M_, 128>>>();
    k_act<<<2, 256>>>(coef, gum);
    k_denp<<<dim3(8, FV), NO>>>(theta, nu);
    k_wfill<<<dim3(8, FV), NO>>>(theta, nu);
    k_p1<<<dim3(16, FV), 256>>>(a);
    k_gemm<<<dim3(16, 8, FV), 256>>>(a, out);
    k_final<<<1, 256>>>(out, out_size);
}

// round 2
// speedup vs baseline: 1.0492x; 1.0492x over previous
#include <cuda_runtime.h>
#include <math.h>

#define F_ 2
#define V_ 4
#define FV 8
#define E_ 2048
#define NI 512
#define NO 512
#define M_ 514
#define GMIN 0.01f
#define GMAX 10.0f
#define PGMIN 1e-4f

// ---------------- scratch (static device globals; no allocation) -------------
__device__ float d_Weff[FV * M_ * NO];     // theta_noisy / denom
__device__ float d_Hm[FV * M_ * NO];       // g_tilde * sign(theta_noisy)
__device__ float d_gtilde[M_ * NO];
__device__ float d_G[NO];                  // sum_m g_tilde[m,n]
__device__ float d_gsumm[M_];              // sum_n g_tilde[m,n]
__device__ float d_denp[FV * 8 * NO];      // partial |theta_noisy| sums over m-chunks
__device__ float4 d_actp[NO];              // chosen pTanh params per column
__device__ float d_p1p[FV * 16];           // p1 partials
__device__ float d_pwp[16 * 8 * FV];       // gemm-block power partials (p2+p3)

__constant__ float c_etas[16] = {
    0.05f, 0.90f, 0.20f, 8.0f,
    0.10f, 0.80f, 0.30f, 5.0f,
    0.00f, 1.00f, 0.25f, 10.0f,
    0.15f, 0.70f, 0.15f, 6.0f};

__device__ __forceinline__ float th_clip(float t) {
    return fminf(fmaxf(t, -GMAX), GMAX);
}
__device__ __forceinline__ float th_fwd(float t) {
    float c = th_clip(t);
    return (fabsf(c) < GMIN) ? 0.0f : c;
}

// packed fp32x2 FMA helpers (sm_103a)
__device__ __forceinline__ void fma2(unsigned long long& d, unsigned long long a,
                                     unsigned long long b) {
    asm("fma.rn.f32x2 %0, %1, %2, %0;" : "+l"(d) : "l"(a), "l"(b));
}
__device__ __forceinline__ float2 unpack2(unsigned long long v) {
    float2 r;
    asm("mov.b64 {%0,%1}, %2;" : "=f"(r.x), "=f"(r.y) : "l"(v));
    return r;
}

// ---------------- g_tilde, G ------------------------------------------------
__global__ void k_gtilde(const float* __restrict__ theta) {
    int n = blockIdx.x;
    int t = threadIdx.x;
    __shared__ float red[128];
    float mn = 1e30f;
    for (int m = t; m < M_; m += 128)
        mn = fminf(mn, fabsf(th_clip(theta[m * NO + n])));
    red[t] = mn;
    __syncthreads();
    for (int s = 64; s > 0; s >>= 1) {
        if (t < s) red[t] = fminf(red[t], red[t + s]);
        __syncthreads();
    }
    float scale = PGMIN / red[0];
    __syncthreads();
    float sum = 0.f;
    for (int m = t; m < M_; m += 128) {
        float g = fabsf(th_clip(theta[m * NO + n])) * scale;
        d_gtilde[m * NO + n] = g;
        sum += g;
    }
    red[t] = sum;
    __syncthreads();
    for (int s = 64; s > 0; s >>= 1) {
        if (t < s) red[t] += red[t + s];
        __syncthreads();
    }
    if (t == 0) d_G[n] = red[0];
}

// ---------------- gsum_m ----------------------------------------------------
__global__ void k_gsumm() {
    int m = blockIdx.x;
    int t = threadIdx.x;
    __shared__ float red[128];
    float s = 0.f;
    for (int n = t; n < NO; n += 128) s += d_gtilde[m * NO + n];
    red[t] = s;
    __syncthreads();
    for (int k = 64; k > 0; k >>= 1) {
        if (t < k) red[t] += red[t + k];
        __syncthreads();
    }
    if (t == 0) d_gsumm[m] = red[0];
}

// ---------------- activation select -----------------------------------------
__global__ void k_act(const float* __restrict__ coef, const float* __restrict__ gum) {
    int n = blockIdx.x * blockDim.x + threadIdx.x;
    if (n >= NO) return;
    float best = -1e30f;
    int bi = 0;
#pragma unroll
    for (int i = 0; i < 4; i++) {
        float c = fminf(fmaxf(coef[i * NO + n], -1.f), 1.f);
        float g = gum[i * NO + n];
        float gn = -logf(-logf(g + 1e-20f) + 1e-20f);
        float v = c + gn;
        if (v > best) { best = v; bi = i; }
    }
    d_actp[n] = make_float4(c_etas[bi * 4 + 0], c_etas[bi * 4 + 1],
                            c_etas[bi * 4 + 2], c_etas[bi * 4 + 3]);
}

// ---------------- denom partials over m-chunks --------------------------------
__global__ void k_denp(const float* __restrict__ theta, const float* __restrict__ nu) {
    int n = threadIdx.x;            // 512 threads
    int c = blockIdx.x;             // 8 chunks
    int fv = blockIdx.y;            // 8
    int m0 = c * 65, m1 = min(M_, m0 + 65);
    float acc = 0.f;
    for (int m = m0; m < m1; m++) {
        float t = th_fwd(theta[m * NO + n]);
        float u = nu[((size_t)fv * M_ + m) * NO + n];
        acc += fabsf(t * (u * 0.2f + 0.9f));
    }
    d_denp[((size_t)fv * 8 + c) * NO + n] = acc;
}

// ---------------- fill Weff, H ------------------------------------------------
__global__ void k_wfill(const float* __restrict__ theta, const float* __restrict__ nu) {
    int n = threadIdx.x;
    int c = blockIdx.x;
    int fv = blockIdx.y;
    float den = 1e-10f;
#pragma unroll
    for (int i = 0; i < 8; i++) den += d_denp[((size_t)fv * 8 + i) * NO + n];
    float inv = 1.f / den;
    int m0 = c * 65, m1 = min(M_, m0 + 65);
    for (int m = m0; m < m1; m++) {
        float t = th_fwd(theta[m * NO + n]);
        float u = nu[((size_t)fv * M_ + m) * NO + n];
        float tn = t * (u * 0.2f + 0.9f);
        size_t idx = ((size_t)fv * M_ + m) * NO + n;
        d_Weff[idx] = tn * inv;
        float s = (tn >= 0.f) ? 1.f : -1.f;
        d_Hm[idx] = d_gtilde[m * NO + n] * s;
    }
}

// ---------------- p1 partials: sum a^2 * gsum_m -------------------------------
__global__ void k_p1(const float* __restrict__ a) {
    __shared__ float gs[NI];
    __shared__ float red[256];
    int t = threadIdx.x;
    for (int i = t; i < NI; i += 256) gs[i] = d_gsumm[i];
    __syncthreads();
    int fv = blockIdx.y, ec = blockIdx.x;
    const float* base = a + ((size_t)fv * E_ + ec * 128) * NI;
    float acc = 0.f;
    for (int e = 0; e < 128; e++) {
        const float* row = base + (size_t)e * NI;
        for (int m = t; m < NI; m += 256) {
            float x = row[m];
            acc += x * x * gs[m];
        }
    }
    red[t] = acc;
    __syncthreads();
    for (int s = 128; s > 0; s >>= 1) {
        if (t < s) red[t] += red[t + s];
        __syncthreads();
    }
    if (t == 0) d_p1p[fv * 16 + ec] = red[0];
}

// ---------------- main fused GEMM: Z = X@Weff, U = X@H, activation + power ----
#define BM 128
#define BN 64
#define BK 8

__global__ void __launch_bounds__(256, 2)
k_gemm(const float* __restrict__ a, float* __restrict__ out) {
    __shared__ __align__(16) float As[BK][BM];
    __shared__ __align__(16) float2 Bw[BK][BN];  // lane-duplicated
    __shared__ __align__(16) float2 Bh[BK][BN];

    int t = threadIdx.x;
    int fv = blockIdx.z;
    int e0 = blockIdx.x * BM;
    int n0 = blockIdx.y * BN;
    int tx = t & 15;   // 16 -> BN/TN(4)
    int ty = t >> 4;   // 16 -> BM/TM(8)

    // A loader: thread -> (row, 4 cols)
    int arow = t >> 1;
    int acol = (t & 1) * 4;
    const float* abase = a + ((size_t)fv * E_ + e0 + arow) * NI;
    // B loader: thread -> (2 rows, 1 col)
    int bn = t & 63;
    int br = t >> 6;

    unsigned long long accz[4][4], accu[4][4];
#pragma unroll
    for (int i = 0; i < 4; i++)
#pragma unroll
        for (int j = 0; j < 4; j++) { accz[i][j] = 0ull; accu[i][j] = 0ull; }

    for (int kt = 0; kt < 65; kt++) {
        int k0 = kt * BK;
        float4 av4;
        if (k0 < 512) {
            av4 = *(const float4*)(abase + k0 + acol);
        } else {  // k0 == 512: x_ext = [.., 1, 0, pad...]
            av4.x = (acol == 0) ? 1.0f : 0.0f;
            av4.y = 0.0f; av4.z = 0.0f; av4.w = 0.0f;
        }
        As[acol + 0][arow] = av4.x;
        As[acol + 1][arow] = av4.y;
        As[acol + 2][arow] = av4.z;
        As[acol + 3][arow] = av4.w;
#pragma unroll
        for (int rr = 0; rr < 2; rr++) {
            int r = br + rr * 4;
            int m = k0 + r;
            float w = 0.f, h = 0.f;
            if (m < M_) {
                size_t idx = ((size_t)fv * M_ + m) * NO + n0 + bn;
                w = d_Weff[idx];
                h = d_Hm[idx];
            }
            Bw[r][bn] = make_float2(w, w);
            Bh[r][bn] = make_float2(h, h);
        }
        __syncthreads();
#pragma unroll
        for (int kk = 0; kk < BK; kk++) {
            const ulonglong2* ap = (const ulonglong2*)&As[kk][ty * 8];
            ulonglong2 a01 = ap[0], a23 = ap[1];
            const ulonglong2* bwp = (const ulonglong2*)&Bw[kk][tx * 4];
            ulonglong2 bw01 = bwp[0], bw23 = bwp[1];
            const ulonglong2* bhp = (const ulonglong2*)&Bh[kk][tx * 4];
            ulonglong2 bh01 = bhp[0], bh23 = bhp[1];
            unsigned long long aa[4] = {a01.x, a01.y, a23.x, a23.y};
            unsigned long long bw_[4] = {bw01.x, bw01.y, bw23.x, bw23.y};
            unsigned long long bh_[4] = {bh01.x, bh01.y, bh23.x, bh23.y};
#pragma unroll
            for (int i = 0; i < 4; i++)
#pragma unroll
                for (int j = 0; j < 4; j++) {
                    fma2(accz[i][j], aa[i], bw_[j]);
                    fma2(accu[i][j], aa[i], bh_[j]);
                }
        }
        __syncthreads();
    }

    // epilogue
    int n_base = n0 + tx * 4;
    int e_base = e0 + ty * 8;
    float4 gv = *(const float4*)&d_G[n_base];
    float G_[4] = {gv.x, gv.y, gv.z, gv.w};
    float4 P[4];
#pragma unroll
    for (int j = 0; j < 4; j++) P[j] = d_actp[n_base + j];

    float pw = 0.f;
#pragma unroll
    for (int ip = 0; ip < 4; ip++) {
        float2 z[4], u[4];
#pragma unroll
        for (int j = 0; j < 4; j++) {
            z[j] = unpack2(accz[ip][j]);
            u[j] = unpack2(accu[ip][j]);
            pw += z[j].x * (z[j].x * G_[j] - 2.f * u[j].x);
            pw += z[j].y * (z[j].y * G_[j] - 2.f * u[j].y);
        }
        float4 o0, o1;
        o0.x = P[0].x + P[0].y * tanhf((z[0].x - P[0].z) * P[0].w);
        o0.y = P[1].x + P[1].y * tanhf((z[1].x - P[1].z) * P[1].w);
        o0.z = P[2].x + P[2].y * tanhf((z[2].x - P[2].z) * P[2].w);
        o0.w = P[3].x + P[3].y * tanhf((z[3].x - P[3].z) * P[3].w);
        o1.x = P[0].x + P[0].y * tanhf((z[0].y - P[0].z) * P[0].w);
        o1.y = P[1].x + P[1].y * tanhf((z[1].y - P[1].z) * P[1].w);
        o1.z = P[2].x + P[2].y * tanhf((z[2].y - P[2].z) * P[2].w);
        o1.w = P[3].x + P[3].y * tanhf((z[3].y - P[3].z) * P[3].w);
        size_t r0 = ((size_t)fv * E_ + e_base + 2 * ip) * NO + n_base;
        *(float4*)&out[r0] = o0;
        *(float4*)&out[r0 + NO] = o1;
    }

    __shared__ float red[256];
    red[t] = pw;
    __syncthreads();
    for (int s = 128; s > 0; s >>= 1) {
        if (t < s) red[t] += red[t + s];
        __syncthreads();
    }
    if (t == 0)
        d_pwp[(blockIdx.z * 8 + blockIdx.y) * 16 + blockIdx.x] = red[0];
}

// ---------------- final: assemble mac_power ----------------------------------
__global__ void k_final(float* __restrict__ out, int out_size) {
    __shared__ float red[256];
    int t = threadIdx.x;
    float s = 0.f;
    for (int i = t; i < 16 * 8 * FV; i += 256) s += d_pwp[i];
    for (int i = t; i < FV * 16; i += 256) s += d_p1p[i];
    red[t] = s;
    __syncthreads();
    for (int k = 128; k > 0; k >>= 1) {
        if (t < k) red[t] += red[t + k];
        __syncthreads();
    }
    if (t == 0) {
        // p1 contribution of the ones-column (m = 512): sx2 = E_ per (f,v)
        float p1_ones = (float)(FV * E_) * d_gsumm[512];
        float power = (red[0] + p1_ones) / (float)(E_ * V_ * F_);
        long long total = (long long)FV * E_ * NO;
        if (out_size > total) out[total] = power;
    }
}

extern "C" void kernel_launch(void* const* d_in, const int* in_sizes, int n_in,
                              void* d_out, int out_size) {
    const float* a     = (const float*)d_in[0];  // a_previous [F,V,E,NI]
    const float* theta = (const float*)d_in[1];  // theta_ [M,NO]
    const float* coef  = (const float*)d_in[2];  // cofficients_act [4,NO]
    const float* nu    = (const float*)d_in[3];  // noise_u [F,V,M,NO]
    const float* gum   = (const float*)d_in[4];  // gumbel_u [4,NO]
    float* out = (float*)d_out;
    (void)in_sizes; (void)n_in;

    k_gtilde<<<NO, 128>>>(theta);
    k_gsumm<<<M_, 128>>>();
    k_act<<<2, 256>>>(coef, gum);
    k_denp<<<dim3(8, FV), NO>>>(theta, nu);
    k_wfill<<<dim3(8, FV), NO>>>(theta, nu);
    k_p1<<<dim3(16, FV), 256>>>(a);
    k_gemm<<<dim3(16, 8, FV), 256>>>(a, out);
    k_final<<<1, 256>>>(out, out_size);
}

// round 4
// speedup vs baseline: 4.1238x; 3.9303x over previous
#include <cuda_runtime.h>
#include <cuda_bf16.h>
#include <math.h>
#include <stdint.h>

#define F_ 2
#define V_ 4
#define FV 8
#define E_ 2048
#define NI 512
#define NO 512
#define M_ 514
#define GMIN 0.01f
#define GMAX 10.0f
#define PGMIN 1e-4f

// ---------------- scratch ------------------------------------------------------
__device__ __align__(16) __nv_bfloat16 d_Ah[FV * E_ * NI];
__device__ __align__(16) __nv_bfloat16 d_Al[FV * E_ * NI];
__device__ __align__(16) __nv_bfloat16 d_Bh[FV * NO * NI];
__device__ __align__(16) __nv_bfloat16 d_Bl[FV * NO * NI];
__device__ __align__(16) __nv_bfloat16 d_Hb[FV * NO * NI];
__device__ float d_gtilde[M_ * NO];
__device__ float d_G[NO];
__device__ float d_gsumm[M_];
__device__ float d_denp[FV * 16 * NO];
__device__ float d_invden[FV * NO];
__device__ float d_fixz[FV * NO];
__device__ float d_fixu[FV * NO];
__device__ float4 d_actp[NO];
__device__ float d_p1p[FV * 16];
__device__ float d_pwp[512];

__constant__ float c_etas[16] = {
    0.05f, 0.90f, 0.20f, 8.0f,
    0.10f, 0.80f, 0.30f, 5.0f,
    0.00f, 1.00f, 0.25f, 10.0f,
    0.15f, 0.70f, 0.15f, 6.0f};

__device__ __forceinline__ float th_clip(float t) {
    return fminf(fmaxf(t, -GMAX), GMAX);
}
__device__ __forceinline__ float th_fwd(float t) {
    float c = th_clip(t);
    return (fabsf(c) < GMIN) ? 0.0f : c;
}

// ---------------- PTX helpers (all base-ISA, no sm_103a-gated features) ---------
__device__ __forceinline__ uint32_t smem_to_u32(const void* p) {
    uint32_t a;
    asm("{ .reg .u64 t; cvta.to.shared.u64 t, %1; cvt.u32.u64 %0, t; }" : "=r"(a) : "l"(p));
    return a;
}
__device__ __forceinline__ uint32_t packbf2(float hi, float lo) {
    uint32_t r;
    asm("cvt.rn.bf16x2.f32 %0, %1, %2;" : "=r"(r) : "f"(hi), "f"(lo));
    return r;
}
__device__ __forceinline__ void cp_async16(uint32_t s, const void* g) {
    asm volatile("cp.async.cg.shared.global [%0], [%1], 16;" :: "r"(s), "l"(g) : "memory");
}
#define CP_COMMIT() asm volatile("cp.async.commit_group;" ::: "memory")
#define CP_WAIT1()  asm volatile("cp.async.wait_group 1;" ::: "memory")
#define CP_WAIT0()  asm volatile("cp.async.wait_group 0;" ::: "memory")

__device__ __forceinline__ void ldm4(uint32_t r[4], uint32_t addr) {
    asm volatile("ldmatrix.sync.aligned.m8n8.x4.shared.b16 {%0,%1,%2,%3}, [%4];"
                 : "=r"(r[0]), "=r"(r[1]), "=r"(r[2]), "=r"(r[3]) : "r"(addr));
}
__device__ __forceinline__ void mma_bf16(float c[4], const uint32_t a[4],
                                         uint32_t b0, uint32_t b1) {
    asm volatile(
        "mma.sync.aligned.m16n8k16.row.col.f32.bf16.bf16.f32 "
        "{%0,%1,%2,%3}, {%4,%5,%6,%7}, {%8,%9}, {%0,%1,%2,%3};"
        : "+f"(c[0]), "+f"(c[1]), "+f"(c[2]), "+f"(c[3])
        : "r"(a[0]), "r"(a[1]), "r"(a[2]), "r"(a[3]), "r"(b0), "r"(b1));
}

// ---------------- g_tilde, G ---------------------------------------------------
__global__ void k_gtilde(const float* __restrict__ theta) {
    int n = blockIdx.x;
    int t = threadIdx.x;
    __shared__ float red[128];
    float mn = 1e30f;
    for (int m = t; m < M_; m += 128)
        mn = fminf(mn, fabsf(th_clip(theta[m * NO + n])));
    red[t] = mn;
    __syncthreads();
    for (int s = 64; s > 0; s >>= 1) {
        if (t < s) red[t] = fminf(red[t], red[t + s]);
        __syncthreads();
    }
    float scale = PGMIN / red[0];
    __syncthreads();
    float sum = 0.f;
    for (int m = t; m < M_; m += 128) {
        float g = fabsf(th_clip(theta[m * NO + n])) * scale;
        d_gtilde[m * NO + n] = g;
        sum += g;
    }
    red[t] = sum;
    __syncthreads();
    for (int s = 64; s > 0; s >>= 1) {
        if (t < s) red[t] += red[t + s];
        __syncthreads();
    }
    if (t == 0) d_G[n] = red[0];
}

__global__ void k_gsumm() {
    int m = blockIdx.x;
    int t = threadIdx.x;
    __shared__ float red[128];
    float s = 0.f;
    for (int n = t; n < NO; n += 128) s += d_gtilde[m * NO + n];
    red[t] = s;
    __syncthreads();
    for (int k = 64; k > 0; k >>= 1) {
        if (t < k) red[t] += red[t + k];
        __syncthreads();
    }
    if (t == 0) d_gsumm[m] = red[0];
}

__global__ void k_act(const float* __restrict__ coef, const float* __restrict__ gum) {
    int n = blockIdx.x * blockDim.x + threadIdx.x;
    if (n >= NO) return;
    float best = -1e30f;
    int bi = 0;
#pragma unroll
    for (int i = 0; i < 4; i++) {
        float c = fminf(fmaxf(coef[i * NO + n], -1.f), 1.f);
        float g = gum[i * NO + n];
        float gn = -logf(-logf(g + 1e-20f) + 1e-20f);
        float v = c + gn;
        if (v > best) { best = v; bi = i; }
    }
    d_actp[n] = make_float4(c_etas[bi * 4 + 0], c_etas[bi * 4 + 1],
                            c_etas[bi * 4 + 2], c_etas[bi * 4 + 3]);
}

// ---------------- denominator partials ------------------------------------------
__global__ void k_denp(const float* __restrict__ theta, const float* __restrict__ nu) {
    int n = threadIdx.x;
    int bx = blockIdx.x;
    int fv = blockIdx.y;
    int m0 = bx * 33, m1 = min(M_, m0 + 33);
    float acc = 0.f;
    for (int m = m0; m < m1; m++) {
        float t = th_fwd(theta[m * NO + n]);
        float u = nu[((size_t)fv * M_ + m) * NO + n];
        acc += fabsf(t * (u * 0.2f + 0.9f));
    }
    d_denp[((size_t)fv * 16 + bx) * NO + n] = acc;
}

// ---------------- invden + exact fp32 fix rows (m = 512) ------------------------
__global__ void k_fix(const float* __restrict__ theta, const float* __restrict__ nu) {
    int fv = blockIdx.x;
    int n = threadIdx.x;
    float den = 1e-10f;
#pragma unroll
    for (int i = 0; i < 16; i++) den += d_denp[((size_t)fv * 16 + i) * NO + n];
    float inv = 1.f / den;
    d_invden[fv * NO + n] = inv;
    float th = th_fwd(theta[512 * NO + n]);
    float u = nu[((size_t)fv * M_ + 512) * NO + n];
    float tn = th * (u * 0.2f + 0.9f);
    d_fixz[fv * NO + n] = tn * inv;
    d_fixu[fv * NO + n] = d_gtilde[512 * NO + n] * (tn >= 0.f ? 1.f : -1.f);
}

// ---------------- B prep: W hi/lo + H, transposed to [n][k] ----------------------
__global__ void k_prepB(const float* __restrict__ theta, const float* __restrict__ nu) {
    __shared__ float sw[64][65], sh[64][65];
    int t = threadIdx.x;
    int mt = blockIdx.x * 64, nt = blockIdx.y * 64, fv = blockIdx.z;
    int nl = t & 63;
    float inv = d_invden[fv * NO + nt + nl];
#pragma unroll 4
    for (int r = 0; r < 16; r++) {
        int ml = (t >> 6) * 16 + r;
        int m = mt + ml, n = nt + nl;
        float th = th_fwd(theta[m * NO + n]);
        float u = nu[((size_t)fv * M_ + m) * NO + n];
        float w = th * (u * 0.2f + 0.9f) * inv;
        sw[ml][nl] = w;
        sh[ml][nl] = d_gtilde[m * NO + n] * (w >= 0.f ? 1.f : -1.f);
    }
    __syncthreads();
    int nr = t >> 2, q = t & 3;
#pragma unroll
    for (int hf = 0; hf < 2; hf++) {
        float wv[8], hv[8];
#pragma unroll
        for (int j = 0; j < 8; j++) {
            wv[j] = sw[q * 16 + hf * 8 + j][nr];
            hv[j] = sh[q * 16 + hf * 8 + j][nr];
        }
        uint32_t hw[4], lw[4], hb[4];
#pragma unroll
        for (int p = 0; p < 4; p++) {
            uint32_t hp = packbf2(wv[2 * p + 1], wv[2 * p]);
            float f0 = __uint_as_float(hp << 16);
            float f1 = __uint_as_float(hp & 0xFFFF0000u);
            hw[p] = hp;
            lw[p] = packbf2(wv[2 * p + 1] - f1, wv[2 * p] - f0);
            hb[p] = packbf2(hv[2 * p + 1], hv[2 * p]);
        }
        size_t eoff = ((size_t)fv * NO + nt + nr) * NI + mt + q * 16 + hf * 8;
        *(uint4*)((char*)d_Bh + eoff * 2) = make_uint4(hw[0], hw[1], hw[2], hw[3]);
        *(uint4*)((char*)d_Bl + eoff * 2) = make_uint4(lw[0], lw[1], lw[2], lw[3]);
        *(uint4*)((char*)d_Hb + eoff * 2) = make_uint4(hb[0], hb[1], hb[2], hb[3]);
    }
}

// ---------------- A prep: bf16 hi/lo + fused p1 partial --------------------------
__global__ void k_prepA(const float* __restrict__ a) {
    __shared__ float gs[NI];
    __shared__ float red[256];
    int t = threadIdx.x;
    int ec = blockIdx.x, fv = blockIdx.y;
    for (int i = t; i < NI; i += 256) gs[i] = d_gsumm[i];
    __syncthreads();
    size_t base = ((size_t)fv * E_ + ec * 128) * NI;
    const float* ab = a + base;
    float acc = 0.f;
    for (int j = 0; j < 64; j++) {
        int flat = j * 256 + t;
        int e = flat >> 7, c4 = flat & 127;
        size_t off = (size_t)e * NI + c4 * 4;
        float4 x = *(const float4*)(ab + off);
        acc += x.x * x.x * gs[c4 * 4 + 0] + x.y * x.y * gs[c4 * 4 + 1] +
               x.z * x.z * gs[c4 * 4 + 2] + x.w * x.w * gs[c4 * 4 + 3];
        uint32_t h0 = packbf2(x.y, x.x);
        uint32_t h1 = packbf2(x.w, x.z);
        float hx = __uint_as_float(h0 << 16);
        float hy = __uint_as_float(h0 & 0xFFFF0000u);
        float hz = __uint_as_float(h1 << 16);
        float hw = __uint_as_float(h1 & 0xFFFF0000u);
        uint32_t l0 = packbf2(x.y - hy, x.x - hx);
        uint32_t l1 = packbf2(x.w - hw, x.z - hz);
        *(uint2*)((char*)d_Ah + (base + off) * 2) = make_uint2(h0, h1);
        *(uint2*)((char*)d_Al + (base + off) * 2) = make_uint2(l0, l1);
    }
    red[t] = acc;
    __syncthreads();
    for (int s = 128; s > 0; s >>= 1) {
        if (t < s) red[t] += red[t + s];
        __syncthreads();
    }
    if (t == 0) d_p1p[fv * 16 + ec] = red[0];
}

// ---------------- main mma.sync GEMM ----------------------------------------------
// CTA 128(E) x 128(N); 8 warps = 2(m) x 4(n); warp 64x32; k-chunks of 32, 2 stages.
// smem stage: 5 matrices x 128 rows x 80B (64B data + 16B pad) = 51200B.
#define ROWB 80
#define MATB 10240
#define STAGEB 51200

__global__ void __launch_bounds__(256, 1)
k_gemm(float* __restrict__ out) {
    extern __shared__ __align__(16) char dsm[];
    uint32_t sb = smem_to_u32(dsm);
    int t = threadIdx.x;
    int wid = t >> 5, lane = t & 31;
    int wm = wid & 1, wn = wid >> 1;
    int fv = blockIdx.z, e0 = blockIdx.y * 128, n0 = blockIdx.x * 128;

    const char* gA  = (const char*)d_Ah + ((size_t)fv * E_ + e0) * NI * 2;
    const char* gAl = (const char*)d_Al + ((size_t)fv * E_ + e0) * NI * 2;
    const char* gB  = (const char*)d_Bh + ((size_t)fv * NO + n0) * NI * 2;
    const char* gBl = (const char*)d_Bl + ((size_t)fv * NO + n0) * NI * 2;
    const char* gH  = (const char*)d_Hb + ((size_t)fv * NO + n0) * NI * 2;

    auto load_chunk = [&](int c, int st) {
        uint32_t base = sb + st * STAGEB;
#pragma unroll
        for (int it = 0; it < 2; it++) {
            int i = t + it * 256;
            int row = i >> 2, j = i & 3;
            uint32_t s = base + row * ROWB + j * 16;
            size_t g = (size_t)row * 1024 + (size_t)c * 64 + j * 16;
            cp_async16(s,            gA + g);
            cp_async16(s + MATB,     gAl + g);
            cp_async16(s + 2 * MATB, gB + g);
            cp_async16(s + 3 * MATB, gBl + g);
            cp_async16(s + 4 * MATB, gH + g);
        }
    };

    float zc[4][4][4], uc[4][4][4];
#pragma unroll
    for (int i = 0; i < 4; i++)
#pragma unroll
        for (int j = 0; j < 4; j++)
#pragma unroll
            for (int k = 0; k < 4; k++) { zc[i][j][k] = 0.f; uc[i][j][k] = 0.f; }

    // per-thread ldmatrix base offsets (lane -> row/colhalf of 16x16 block)
    uint32_t aoff = (wm * 64 + (lane & 15)) * ROWB + (lane >> 4) * 16;
    uint32_t boff = (wn * 32 + (lane & 15)) * ROWB + (lane >> 4) * 16;

    load_chunk(0, 0); CP_COMMIT();
    load_chunk(1, 1); CP_COMMIT();

    for (int c = 0; c < 16; c++) {
        int st = c & 1;
        if (c < 15) { CP_WAIT1(); } else { CP_WAIT0(); }
        __syncthreads();
        uint32_t base = sb + st * STAGEB;
#pragma unroll
        for (int ks = 0; ks < 2; ks++) {
            uint32_t ah[4][4], al[4][4];
#pragma unroll
            for (int mt = 0; mt < 4; mt++) {
                uint32_t ad = base + aoff + mt * (16 * ROWB) + ks * 32;
                ldm4(ah[mt], ad);
                ldm4(al[mt], ad + MATB);
            }
            uint32_t bh[2][4], bl[2][4], hb[2][4];
#pragma unroll
            for (int pp = 0; pp < 2; pp++) {
                uint32_t bd = base + 2 * MATB + boff + pp * (16 * ROWB) + ks * 32;
                ldm4(bh[pp], bd);
                ldm4(bl[pp], bd + MATB);
                ldm4(hb[pp], bd + 2 * MATB);
            }
#pragma unroll
            for (int mt = 0; mt < 4; mt++)
#pragma unroll
                for (int nt = 0; nt < 4; nt++) {
                    int pp = nt >> 1, s = nt & 1;
                    mma_bf16(zc[mt][nt], ah[mt], bh[pp][s], bh[pp][s + 2]);
                    mma_bf16(zc[mt][nt], ah[mt], bl[pp][s], bl[pp][s + 2]);
                    mma_bf16(zc[mt][nt], al[mt], bh[pp][s], bh[pp][s + 2]);
                    mma_bf16(uc[mt][nt], ah[mt], hb[pp][s], hb[pp][s + 2]);
                }
        }
        __syncthreads();
        if (c + 2 < 16) { load_chunk(c + 2, st); CP_COMMIT(); }
    }

    // ---------------- epilogue ----------------
    float pw = 0.f;
    int lrow = lane >> 2, lcol = (lane & 3) * 2;
#pragma unroll
    for (int nt = 0; nt < 4; nt++) {
        int nc = n0 + wn * 32 + nt * 8 + lcol;
        float fz0 = d_fixz[fv * NO + nc],     fz1 = d_fixz[fv * NO + nc + 1];
        float fu0 = d_fixu[fv * NO + nc],     fu1 = d_fixu[fv * NO + nc + 1];
        float G0  = d_G[nc],                  G1  = d_G[nc + 1];
        float4 P0 = d_actp[nc],               P1  = d_actp[nc + 1];
#pragma unroll
        for (int mt = 0; mt < 4; mt++) {
            int r0 = e0 + wm * 64 + mt * 16 + lrow;
#pragma unroll
            for (int h = 0; h < 2; h++) {
                float z0 = zc[mt][nt][2 * h + 0] + fz0;
                float z1 = zc[mt][nt][2 * h + 1] + fz1;
                float u0 = uc[mt][nt][2 * h + 0] + fu0;
                float u1 = uc[mt][nt][2 * h + 1] + fu1;
                pw += z0 * (z0 * G0 - 2.f * u0);
                pw += z1 * (z1 * G1 - 2.f * u1);
                float2 o;
                o.x = P0.x + P0.y * tanhf((z0 - P0.z) * P0.w);
                o.y = P1.x + P1.y * tanhf((z1 - P1.z) * P1.w);
                *(float2*)(out + ((size_t)fv * E_ + r0 + h * 8) * NO + nc) = o;
            }
        }
    }

    __shared__ float red[256];
    red[t] = pw;
    __syncthreads();
    for (int s = 128; s > 0; s >>= 1) {
        if (t < s) red[t] += red[t + s];
        __syncthreads();
    }
    if (t == 0)
        d_pwp[(blockIdx.z * 4 + blockIdx.x) * 16 + blockIdx.y] = red[0];
}

// ---------------- final ----------------------------------------------------------
__global__ void k_final(float* __restrict__ out, int out_size) {
    __shared__ float red[256];
    int t = threadIdx.x;
    float s = 0.f;
    for (int i = t; i < 512; i += 256) s += d_pwp[i];
    for (int i = t; i < FV * 16; i += 256) s += d_p1p[i];
    red[t] = s;
    __syncthreads();
    for (int k = 128; k > 0; k >>= 1) {
        if (t < k) red[t] += red[t + k];
        __syncthreads();
    }
    if (t == 0) {
        float p1_ones = (float)(FV * E_) * d_gsumm[512];
        float power = (red[0] + p1_ones) / (float)(E_ * V_ * F_);
        long long total = (long long)FV * E_ * NO;
        if (out_size > total) out[total] = power;
    }
}

extern "C" void kernel_launch(void* const* d_in, const int* in_sizes, int n_in,
                              void* d_out, int out_size) {
    const float* a     = (const float*)d_in[0];
    const float* theta = (const float*)d_in[1];
    const float* coef  = (const float*)d_in[2];
    const float* nu    = (const float*)d_in[3];
    const float* gum   = (const float*)d_in[4];
    float* out = (float*)d_out;
    (void)in_sizes; (void)n_in;

    static int smem_set = 0;
    if (!smem_set) {
        cudaFuncSetAttribute(k_gemm, cudaFuncAttributeMaxDynamicSharedMemorySize,
                             2 * STAGEB);
        smem_set = 1;
    }

    k_gtilde<<<NO, 128>>>(theta);
    k_gsumm<<<M_, 128>>>();
    k_act<<<2, 256>>>(coef, gum);
    k_denp<<<dim3(16, FV), 512>>>(theta, nu);
    k_fix<<<FV, 512>>>(theta, nu);
    k_prepB<<<dim3(8, 8, FV), 256>>>(theta, nu);
    k_prepA<<<dim3(16, FV), 256>>>(a);
    k_gemm<<<dim3(4, 16, FV), 256, 2 * STAGEB>>>(out);
    k_final<<<1, 256>>>(out, out_size);
}

// round 5
// speedup vs baseline: 4.1303x; 1.0016x over previous
#include <cuda_runtime.h>
#include <cuda_bf16.h>
#include <math.h>
#include <stdint.h>

#define F_ 2
#define V_ 4
#define FV 8
#define E_ 2048
#define NI 512
#define NO 512
#define M_ 514
#define GMIN 0.01f
#define GMAX 10.0f
#define PGMIN 1e-4f

// ---------------- scratch ------------------------------------------------------
__device__ __align__(16) __nv_bfloat16 d_Ah[FV * E_ * NI];
__device__ __align__(16) __nv_bfloat16 d_Al[FV * E_ * NI];
__device__ __align__(16) __nv_bfloat16 d_Bh[FV * NO * NI];
__device__ __align__(16) __nv_bfloat16 d_Bl[FV * NO * NI];
__device__ __align__(16) __nv_bfloat16 d_Hb[FV * NO * NI];
__device__ float d_gtilde[M_ * NO];
__device__ float d_G[NO];
__device__ float d_gsumm[M_];
__device__ float d_denp[FV * 32 * NO];
__device__ float d_invden[FV * NO];
__device__ float d_fixz[FV * NO];
__device__ float d_fixu[FV * NO];
__device__ float4 d_actp[NO];
__device__ float d_p1p[FV * 16];
__device__ float d_pwp[512];

__constant__ float c_etas[16] = {
    0.05f, 0.90f, 0.20f, 8.0f,
    0.10f, 0.80f, 0.30f, 5.0f,
    0.00f, 1.00f, 0.25f, 10.0f,
    0.15f, 0.70f, 0.15f, 6.0f};

__device__ __forceinline__ float th_clip(float t) {
    return fminf(fmaxf(t, -GMAX), GMAX);
}
__device__ __forceinline__ float th_fwd(float t) {
    float c = th_clip(t);
    return (fabsf(c) < GMIN) ? 0.0f : c;
}

// ---------------- PTX helpers (base ISA only) -----------------------------------
__device__ __forceinline__ uint32_t smem_to_u32(const void* p) {
    uint32_t a;
    asm("{ .reg .u64 t; cvta.to.shared.u64 t, %1; cvt.u32.u64 %0, t; }" : "=r"(a) : "l"(p));
    return a;
}
__device__ __forceinline__ uint32_t packbf2(float hi, float lo) {
    uint32_t r;
    asm("cvt.rn.bf16x2.f32 %0, %1, %2;" : "=r"(r) : "f"(hi), "f"(lo));
    return r;
}
__device__ __forceinline__ void cp_async16(uint32_t s, const void* g) {
    asm volatile("cp.async.cg.shared.global [%0], [%1], 16;" :: "r"(s), "l"(g) : "memory");
}
#define CP_COMMIT() asm volatile("cp.async.commit_group;" ::: "memory")
#define CP_WAIT1()  asm volatile("cp.async.wait_group 1;" ::: "memory")
#define CP_WAIT0()  asm volatile("cp.async.wait_group 0;" ::: "memory")

__device__ __forceinline__ void ldm4(uint32_t r[4], uint32_t addr) {
    asm volatile("ldmatrix.sync.aligned.m8n8.x4.shared.b16 {%0,%1,%2,%3}, [%4];"
                 : "=r"(r[0]), "=r"(r[1]), "=r"(r[2]), "=r"(r[3]) : "r"(addr));
}
__device__ __forceinline__ void mma_bf16(float c[4], const uint32_t a[4],
                                         uint32_t b0, uint32_t b1) {
    asm volatile(
        "mma.sync.aligned.m16n8k16.row.col.f32.bf16.bf16.f32 "
        "{%0,%1,%2,%3}, {%4,%5,%6,%7}, {%8,%9}, {%0,%1,%2,%3};"
        : "+f"(c[0]), "+f"(c[1]), "+f"(c[2]), "+f"(c[3])
        : "r"(a[0]), "r"(a[1]), "r"(a[2]), "r"(a[3]), "r"(b0), "r"(b1));
}

// ---------------- g_tilde, G ---------------------------------------------------
__global__ void k_gtilde(const float* __restrict__ theta) {
    int n = blockIdx.x;
    int t = threadIdx.x;
    __shared__ float red[128];
    float mn = 1e30f;
    for (int m = t; m < M_; m += 128)
        mn = fminf(mn, fabsf(th_clip(theta[m * NO + n])));
    red[t] = mn;
    __syncthreads();
    for (int s = 64; s > 0; s >>= 1) {
        if (t < s) red[t] = fminf(red[t], red[t + s]);
        __syncthreads();
    }
    float scale = PGMIN / red[0];
    __syncthreads();
    float sum = 0.f;
    for (int m = t; m < M_; m += 128) {
        float g = fabsf(th_clip(theta[m * NO + n])) * scale;
        d_gtilde[m * NO + n] = g;
        sum += g;
    }
    red[t] = sum;
    __syncthreads();
    for (int s = 64; s > 0; s >>= 1) {
        if (t < s) red[t] += red[t + s];
        __syncthreads();
    }
    if (t == 0) d_G[n] = red[0];
}

__global__ void k_gsumm() {
    int m = blockIdx.x;
    int t = threadIdx.x;
    __shared__ float red[128];
    float s = 0.f;
    for (int n = t; n < NO; n += 128) s += d_gtilde[m * NO + n];
    red[t] = s;
    __syncthreads();
    for (int k = 64; k > 0; k >>= 1) {
        if (t < k) red[t] += red[t + k];
        __syncthreads();
    }
    if (t == 0) d_gsumm[m] = red[0];
}

__global__ void k_act(const float* __restrict__ coef, const float* __restrict__ gum) {
    int n = blockIdx.x * blockDim.x + threadIdx.x;
    if (n >= NO) return;
    float best = -1e30f;
    int bi = 0;
#pragma unroll
    for (int i = 0; i < 4; i++) {
        float c = fminf(fmaxf(coef[i * NO + n], -1.f), 1.f);
        float g = gum[i * NO + n];
        float gn = -logf(-logf(g + 1e-20f) + 1e-20f);
        float v = c + gn;
        if (v > best) { best = v; bi = i; }
    }
    d_actp[n] = make_float4(c_etas[bi * 4 + 0], c_etas[bi * 4 + 1],
                            c_etas[bi * 4 + 2], c_etas[bi * 4 + 3]);
}

// ---------------- denominator partials ------------------------------------------
__global__ void k_denp(const float* __restrict__ theta, const float* __restrict__ nu) {
    int n = threadIdx.x;
    int bx = blockIdx.x;   // 32 chunks of 17
    int fv = blockIdx.y;
    int m0 = bx * 17, m1 = min(M_, m0 + 17);
    float acc = 0.f;
    for (int m = m0; m < m1; m++) {
        float t = th_fwd(theta[m * NO + n]);
        float u = nu[((size_t)fv * M_ + m) * NO + n];
        acc += fabsf(t * (u * 0.2f + 0.9f));
    }
    d_denp[((size_t)fv * 32 + bx) * NO + n] = acc;
}

// ---------------- invden + exact fp32 fix rows (m = 512) ------------------------
__global__ void k_fix(const float* __restrict__ theta, const float* __restrict__ nu) {
    int fv = blockIdx.x;
    int n = threadIdx.x;
    float den = 1e-10f;
#pragma unroll
    for (int i = 0; i < 32; i++) den += d_denp[((size_t)fv * 32 + i) * NO + n];
    float inv = 1.f / den;
    d_invden[fv * NO + n] = inv;
    float th = th_fwd(theta[512 * NO + n]);
    float u = nu[((size_t)fv * M_ + 512) * NO + n];
    float tn = th * (u * 0.2f + 0.9f);
    d_fixz[fv * NO + n] = tn * inv;
    d_fixu[fv * NO + n] = d_gtilde[512 * NO + n] * (tn >= 0.f ? 1.f : -1.f);
}

// ---------------- B prep: W hi/lo + H, transposed to [n][k] ----------------------
__global__ void k_prepB(const float* __restrict__ theta, const float* __restrict__ nu) {
    __shared__ float sw[64][65], sh[64][65];
    int t = threadIdx.x;
    int mt = blockIdx.x * 64, nt = blockIdx.y * 64, fv = blockIdx.z;
    int nl = t & 63;
    float inv = d_invden[fv * NO + nt + nl];
#pragma unroll 4
    for (int r = 0; r < 16; r++) {
        int ml = (t >> 6) * 16 + r;
        int m = mt + ml, n = nt + nl;
        float th = th_fwd(theta[m * NO + n]);
        float u = nu[((size_t)fv * M_ + m) * NO + n];
        float w = th * (u * 0.2f + 0.9f) * inv;
        sw[ml][nl] = w;
        sh[ml][nl] = d_gtilde[m * NO + n] * (w >= 0.f ? 1.f : -1.f);
    }
    __syncthreads();
    int nr = t >> 2, q = t & 3;
#pragma unroll
    for (int hf = 0; hf < 2; hf++) {
        float wv[8], hv[8];
#pragma unroll
        for (int j = 0; j < 8; j++) {
            wv[j] = sw[q * 16 + hf * 8 + j][nr];
            hv[j] = sh[q * 16 + hf * 8 + j][nr];
        }
        uint32_t hw[4], lw[4], hb[4];
#pragma unroll
        for (int p = 0; p < 4; p++) {
            uint32_t hp = packbf2(wv[2 * p + 1], wv[2 * p]);
            float f0 = __uint_as_float(hp << 16);
            float f1 = __uint_as_float(hp & 0xFFFF0000u);
            hw[p] = hp;
            lw[p] = packbf2(wv[2 * p + 1] - f1, wv[2 * p] - f0);
            hb[p] = packbf2(hv[2 * p + 1], hv[2 * p]);
        }
        size_t eoff = ((size_t)fv * NO + nt + nr) * NI + mt + q * 16 + hf * 8;
        *(uint4*)((char*)d_Bh + eoff * 2) = make_uint4(hw[0], hw[1], hw[2], hw[3]);
        *(uint4*)((char*)d_Bl + eoff * 2) = make_uint4(lw[0], lw[1], lw[2], lw[3]);
        *(uint4*)((char*)d_Hb + eoff * 2) = make_uint4(hb[0], hb[1], hb[2], hb[3]);
    }
}

// ---------------- A prep: bf16 hi/lo + fused p1 partial --------------------------
__global__ void k_prepA(const float* __restrict__ a) {
    __shared__ float gs[NI];
    __shared__ float red[256];
    int t = threadIdx.x;
    int ec = blockIdx.x, fv = blockIdx.y;
    for (int i = t; i < NI; i += 256) gs[i] = d_gsumm[i];
    __syncthreads();
    size_t base = ((size_t)fv * E_ + ec * 128) * NI;
    const float* ab = a + base;
    float acc = 0.f;
    for (int j = 0; j < 64; j++) {
        int flat = j * 256 + t;
        int e = flat >> 7, c4 = flat & 127;
        size_t off = (size_t)e * NI + c4 * 4;
        float4 x = *(const float4*)(ab + off);
        acc += x.x * x.x * gs[c4 * 4 + 0] + x.y * x.y * gs[c4 * 4 + 1] +
               x.z * x.z * gs[c4 * 4 + 2] + x.w * x.w * gs[c4 * 4 + 3];
        uint32_t h0 = packbf2(x.y, x.x);
        uint32_t h1 = packbf2(x.w, x.z);
        float hx = __uint_as_float(h0 << 16);
        float hy = __uint_as_float(h0 & 0xFFFF0000u);
        float hz = __uint_as_float(h1 << 16);
        float hw = __uint_as_float(h1 & 0xFFFF0000u);
        uint32_t l0 = packbf2(x.y - hy, x.x - hx);
        uint32_t l1 = packbf2(x.w - hw, x.z - hz);
        *(uint2*)((char*)d_Ah + (base + off) * 2) = make_uint2(h0, h1);
        *(uint2*)((char*)d_Al + (base + off) * 2) = make_uint2(l0, l1);
    }
    red[t] = acc;
    __syncthreads();
    for (int s = 128; s > 0; s >>= 1) {
        if (t < s) red[t] += red[t + s];
        __syncthreads();
    }
    if (t == 0) d_p1p[fv * 16 + ec] = red[0];
}

// ---------------- main mma.sync GEMM ----------------------------------------------
// CTA 128(E) x 128(N); 8 warps = 2(m) x 4(n); warp 64x32; k-chunks of 32, 3 stages.
#define ROWB 80
#define MATB 10240
#define STAGEB 51200

__global__ void __launch_bounds__(256, 1)
k_gemm(float* __restrict__ out) {
    extern __shared__ __align__(16) char dsm[];
    uint32_t sb = smem_to_u32(dsm);
    int t = threadIdx.x;
    int wid = t >> 5, lane = t & 31;
    int wm = wid & 1, wn = wid >> 1;
    int fv = blockIdx.z, e0 = blockIdx.y * 128, n0 = blockIdx.x * 128;

    const char* gA  = (const char*)d_Ah + ((size_t)fv * E_ + e0) * NI * 2;
    const char* gAl = (const char*)d_Al + ((size_t)fv * E_ + e0) * NI * 2;
    const char* gB  = (const char*)d_Bh + ((size_t)fv * NO + n0) * NI * 2;
    const char* gBl = (const char*)d_Bl + ((size_t)fv * NO + n0) * NI * 2;
    const char* gH  = (const char*)d_Hb + ((size_t)fv * NO + n0) * NI * 2;

    auto load_chunk = [&](int c, uint32_t base) {
#pragma unroll
        for (int it = 0; it < 2; it++) {
            int i = t + it * 256;
            int row = i >> 2, j = i & 3;
            uint32_t s = base + row * ROWB + j * 16;
            size_t g = (size_t)row * 1024 + (size_t)c * 64 + j * 16;
            cp_async16(s,            gA + g);
            cp_async16(s + MATB,     gAl + g);
            cp_async16(s + 2 * MATB, gB + g);
            cp_async16(s + 3 * MATB, gBl + g);
            cp_async16(s + 4 * MATB, gH + g);
        }
    };

    float zc[4][4][4], uc[4][4][4];
#pragma unroll
    for (int i = 0; i < 4; i++)
#pragma unroll
        for (int j = 0; j < 4; j++)
#pragma unroll
            for (int k = 0; k < 4; k++) { zc[i][j][k] = 0.f; uc[i][j][k] = 0.f; }

    uint32_t aoff = (wm * 64 + (lane & 15)) * ROWB + (lane >> 4) * 16;
    uint32_t boff = (wn * 32 + (lane & 15)) * ROWB + (lane >> 4) * 16;

    load_chunk(0, sb);          CP_COMMIT();
    load_chunk(1, sb + STAGEB); CP_COMMIT();

    for (int c = 0; c < 16; c++) {
        uint32_t base = sb + (uint32_t)(c % 3) * STAGEB;
        if (c < 15) { CP_WAIT1(); } else { CP_WAIT0(); }
        __syncthreads();
        // eager prefetch: chunk c+2 into the buffer freed by compute(c-1)
        if (c + 2 < 16) {
            load_chunk(c + 2, sb + (uint32_t)((c + 2) % 3) * STAGEB);
            CP_COMMIT();
        }
#pragma unroll
        for (int ks = 0; ks < 2; ks++) {
            uint32_t ah[4][4], al[4][4];
#pragma unroll
            for (int mt = 0; mt < 4; mt++) {
                uint32_t ad = base + aoff + mt * (16 * ROWB) + ks * 32;
                ldm4(ah[mt], ad);
                ldm4(al[mt], ad + MATB);
            }
            uint32_t bh[2][4], bl[2][4], hb[2][4];
#pragma unroll
            for (int pp = 0; pp < 2; pp++) {
                uint32_t bd = base + 2 * MATB + boff + pp * (16 * ROWB) + ks * 32;
                ldm4(bh[pp], bd);
                ldm4(bl[pp], bd + MATB);
                ldm4(hb[pp], bd + 2 * MATB);
            }
#pragma unroll
            for (int mt = 0; mt < 4; mt++)
#pragma unroll
                for (int nt = 0; nt < 4; nt++) {
                    int pp = nt >> 1, s = nt & 1;
                    mma_bf16(zc[mt][nt], ah[mt], bh[pp][s], bh[pp][s + 2]);
                    mma_bf16(zc[mt][nt], ah[mt], bl[pp][s], bl[pp][s + 2]);
                    mma_bf16(zc[mt][nt], al[mt], bh[pp][s], bh[pp][s + 2]);
                    mma_bf16(uc[mt][nt], ah[mt], hb[pp][s], hb[pp][s + 2]);
                }
        }
    }

    // ---------------- epilogue ----------------
    float pw = 0.f;
    int lrow = lane >> 2, lcol = (lane & 3) * 2;
#pragma unroll
    for (int nt = 0; nt < 4; nt++) {
        int nc = n0 + wn * 32 + nt * 8 + lcol;
        float fz0 = d_fixz[fv * NO + nc],     fz1 = d_fixz[fv * NO + nc + 1];
        float fu0 = d_fixu[fv * NO + nc],     fu1 = d_fixu[fv * NO + nc + 1];
        float G0  = d_G[nc],                  G1  = d_G[nc + 1];
        float4 P0 = d_actp[nc],               P1  = d_actp[nc + 1];
#pragma unroll
        for (int mt = 0; mt < 4; mt++) {
            int r0 = e0 + wm * 64 + mt * 16 + lrow;
#pragma unroll
            for (int h = 0; h < 2; h++) {
                float z0 = zc[mt][nt][2 * h + 0] + fz0;
                float z1 = zc[mt][nt][2 * h + 1] + fz1;
                float u0 = uc[mt][nt][2 * h + 0] + fu0;
                float u1 = uc[mt][nt][2 * h + 1] + fu1;
                pw += z0 * (z0 * G0 - 2.f * u0);
                pw += z1 * (z1 * G1 - 2.f * u1);
                float2 o;
                o.x = P0.x + P0.y * tanhf((z0 - P0.z) * P0.w);
                o.y = P1.x + P1.y * tanhf((z1 - P1.z) * P1.w);
                *(float2*)(out + ((size_t)fv * E_ + r0 + h * 8) * NO + nc) = o;
            }
        }
    }

    __shared__ float red[256];
    red[t] = pw;
    __syncthreads();
    for (int s = 128; s > 0; s >>= 1) {
        if (t < s) red[t] += red[t + s];
        __syncthreads();
    }
    if (t == 0)
        d_pwp[(blockIdx.z * 4 + blockIdx.x) * 16 + blockIdx.y] = red[0];
}

// ---------------- final ----------------------------------------------------------
__global__ void k_final(float* __restrict__ out, int out_size) {
    __shared__ float red[256];
    int t = threadIdx.x;
    float s = 0.f;
    for (int i = t; i < 512; i += 256) s += d_pwp[i];
    for (int i = t; i < FV * 16; i += 256) s += d_p1p[i];
    red[t] = s;
    __syncthreads();
    for (int k = 128; k > 0; k >>= 1) {
        if (t < k) red[t] += red[t + k];
        __syncthreads();
    }
    if (t == 0) {
        float p1_ones = (float)(FV * E_) * d_gsumm[512];
        float power = (red[0] + p1_ones) / (float)(E_ * V_ * F_);
        long long total = (long long)FV * E_ * NO;
        if (out_size > total) out[total] = power;
    }
}

extern "C" void kernel_launch(void* const* d_in, const int* in_sizes, int n_in,
                              void* d_out, int out_size) {
    const float* a     = (const float*)d_in[0];
    const float* theta = (const float*)d_in[1];
    const float* coef  = (const float*)d_in[2];
    const float* nu    = (const float*)d_in[3];
    const float* gum   = (const float*)d_in[4];
    float* out = (float*)d_out;
    (void)in_sizes; (void)n_in;

    static int smem_set = 0;
    if (!smem_set) {
        cudaFuncSetAttribute(k_gemm, cudaFuncAttributeMaxDynamicSharedMemorySize,
                             3 * STAGEB);
        smem_set = 1;
    }

    k_gtilde<<<NO, 128>>>(theta);
    k_gsumm<<<M_, 128>>>();
    k_act<<<2, 256>>>(coef, gum);
    k_denp<<<dim3(32, FV), 512>>>(theta, nu);
    k_fix<<<FV, 512>>>(theta, nu);
    k_prepB<<<dim3(8, 8, FV), 256>>>(theta, nu);
    k_prepA<<<dim3(16, FV), 256>>>(a);
    k_gemm<<<dim3(4, 16, FV), 256, 3 * STAGEB>>>(out);
    k_final<<<1, 256>>>(out, out_size);
}

// round 6
// speedup vs baseline: 5.8581x; 1.4183x over previous
#include <cuda_runtime.h>
#include <cuda_fp16.h>
#include <math.h>
#include <stdint.h>

#define F_ 2
#define V_ 4
#define FV 8
#define E_ 2048
#define NI 512
#define NO 512
#define M_ 514
#define GMIN 0.01f
#define GMAX 10.0f
#define PGMIN 1e-4f

// ---------------- scratch ------------------------------------------------------
__device__ __align__(16) unsigned short d_Ah[FV * E_ * NI];   // x fp16 [fv][e][k]
__device__ __align__(16) unsigned short d_Bw[FV * NO * NI];   // W fp16 [fv][n][k]
__device__ __align__(16) unsigned short d_Hb[FV * NO * NI];   // H fp16 [fv][n][k]
__device__ float d_gtilde[M_ * NO];
__device__ float d_G[NO];
__device__ float d_gsumm[M_];
__device__ float d_denp[FV * 32 * NO];
__device__ float d_invden[FV * NO];
__device__ float d_fixz[FV * NO];
__device__ float d_fixu[FV * NO];
__device__ float4 d_actp[NO];
__device__ float d_p1p[FV * 16];
__device__ float d_pwp[512];

__constant__ float c_etas[16] = {
    0.05f, 0.90f, 0.20f, 8.0f,
    0.10f, 0.80f, 0.30f, 5.0f,
    0.00f, 1.00f, 0.25f, 10.0f,
    0.15f, 0.70f, 0.15f, 6.0f};

__device__ __forceinline__ float th_clip(float t) {
    return fminf(fmaxf(t, -GMAX), GMAX);
}
__device__ __forceinline__ float th_fwd(float t) {
    float c = th_clip(t);
    return (fabsf(c) < GMIN) ? 0.0f : c;
}

// ---------------- PTX helpers (base ISA only) -----------------------------------
__device__ __forceinline__ uint32_t smem_to_u32(const void* p) {
    uint32_t a;
    asm("{ .reg .u64 t; cvta.to.shared.u64 t, %1; cvt.u32.u64 %0, t; }" : "=r"(a) : "l"(p));
    return a;
}
__device__ __forceinline__ uint32_t packh2(float hi, float lo) {
    uint32_t r;
    asm("cvt.rn.f16x2.f32 %0, %1, %2;" : "=r"(r) : "f"(hi), "f"(lo));
    return r;
}
__device__ __forceinline__ void cp_async16(uint32_t s, const void* g) {
    asm volatile("cp.async.cg.shared.global [%0], [%1], 16;" :: "r"(s), "l"(g) : "memory");
}
#define CP_COMMIT() asm volatile("cp.async.commit_group;" ::: "memory")
#define CP_WAIT1()  asm volatile("cp.async.wait_group 1;" ::: "memory")
#define CP_WAIT0()  asm volatile("cp.async.wait_group 0;" ::: "memory")

__device__ __forceinline__ void ldm4(uint32_t r[4], uint32_t addr) {
    asm volatile("ldmatrix.sync.aligned.m8n8.x4.shared.b16 {%0,%1,%2,%3}, [%4];"
                 : "=r"(r[0]), "=r"(r[1]), "=r"(r[2]), "=r"(r[3]) : "r"(addr));
}
__device__ __forceinline__ void mma_f16(float c[4], const uint32_t a[4],
                                        uint32_t b0, uint32_t b1) {
    asm volatile(
        "mma.sync.aligned.m16n8k16.row.col.f32.f16.f16.f32 "
        "{%0,%1,%2,%3}, {%4,%5,%6,%7}, {%8,%9}, {%0,%1,%2,%3};"
        : "+f"(c[0]), "+f"(c[1]), "+f"(c[2]), "+f"(c[3])
        : "r"(a[0]), "r"(a[1]), "r"(a[2]), "r"(a[3]), "r"(b0), "r"(b1));
}

// ---------------- g_tilde, G ---------------------------------------------------
__global__ void k_gtilde(const float* __restrict__ theta) {
    int n = blockIdx.x;
    int t = threadIdx.x;
    __shared__ float red[128];
    float mn = 1e30f;
    for (int m = t; m < M_; m += 128)
        mn = fminf(mn, fabsf(th_clip(theta[m * NO + n])));
    red[t] = mn;
    __syncthreads();
    for (int s = 64; s > 0; s >>= 1) {
        if (t < s) red[t] = fminf(red[t], red[t + s]);
        __syncthreads();
    }
    float scale = PGMIN / red[0];
    __syncthreads();
    float sum = 0.f;
    for (int m = t; m < M_; m += 128) {
        float g = fabsf(th_clip(theta[m * NO + n])) * scale;
        d_gtilde[m * NO + n] = g;
        sum += g;
    }
    red[t] = sum;
    __syncthreads();
    for (int s = 64; s > 0; s >>= 1) {
        if (t < s) red[t] += red[t + s];
        __syncthreads();
    }
    if (t == 0) d_G[n] = red[0];
}

__global__ void k_gsumm() {
    int m = blockIdx.x;
    int t = threadIdx.x;
    __shared__ float red[128];
    float s = 0.f;
    for (int n = t; n < NO; n += 128) s += d_gtilde[m * NO + n];
    red[t] = s;
    __syncthreads();
    for (int k = 64; k > 0; k >>= 1) {
        if (t < k) red[t] += red[t + k];
        __syncthreads();
    }
    if (t == 0) d_gsumm[m] = red[0];
}

__global__ void k_act(const float* __restrict__ coef, const float* __restrict__ gum) {
    int n = blockIdx.x * blockDim.x + threadIdx.x;
    if (n >= NO) return;
    float best = -1e30f;
    int bi = 0;
#pragma unroll
    for (int i = 0; i < 4; i++) {
        float c = fminf(fmaxf(coef[i * NO + n], -1.f), 1.f);
        float g = gum[i * NO + n];
        float gn = -logf(-logf(g + 1e-20f) + 1e-20f);
        float v = c + gn;
        if (v > best) { best = v; bi = i; }
    }
    d_actp[n] = make_float4(c_etas[bi * 4 + 0], c_etas[bi * 4 + 1],
                            c_etas[bi * 4 + 2], c_etas[bi * 4 + 3]);
}

// ---------------- denominator partials ------------------------------------------
__global__ void k_denp(const float* __restrict__ theta, const float* __restrict__ nu) {
    int n = threadIdx.x;
    int bx = blockIdx.x;
    int fv = blockIdx.y;
    int m0 = bx * 17, m1 = min(M_, m0 + 17);
    float acc = 0.f;
    for (int m = m0; m < m1; m++) {
        float t = th_fwd(theta[m * NO + n]);
        float u = nu[((size_t)fv * M_ + m) * NO + n];
        acc += fabsf(t * (u * 0.2f + 0.9f));
    }
    d_denp[((size_t)fv * 32 + bx) * NO + n] = acc;
}

// ---------------- invden + exact fp32 fix rows (m = 512) ------------------------
__global__ void k_fix(const float* __restrict__ theta, const float* __restrict__ nu) {
    int fv = blockIdx.x;
    int n = threadIdx.x;
    float den = 1e-10f;
#pragma unroll
    for (int i = 0; i < 32; i++) den += d_denp[((size_t)fv * 32 + i) * NO + n];
    float inv = 1.f / den;
    d_invden[fv * NO + n] = inv;
    float th = th_fwd(theta[512 * NO + n]);
    float u = nu[((size_t)fv * M_ + 512) * NO + n];
    float tn = th * (u * 0.2f + 0.9f);
    d_fixz[fv * NO + n] = tn * inv;
    d_fixu[fv * NO + n] = d_gtilde[512 * NO + n] * (tn >= 0.f ? 1.f : -1.f);
}

// ---------------- B prep: W + H fp16, transposed to [n][k] -----------------------
__global__ void k_prepB(const float* __restrict__ theta, const float* __restrict__ nu) {
    __shared__ float sw[64][65], sh[64][65];
    int t = threadIdx.x;
    int mt = blockIdx.x * 64, nt = blockIdx.y * 64, fv = blockIdx.z;
    int nl = t & 63;
    float inv = d_invden[fv * NO + nt + nl];
#pragma unroll 4
    for (int r = 0; r < 16; r++) {
        int ml = (t >> 6) * 16 + r;
        int m = mt + ml, n = nt + nl;
        float th = th_fwd(theta[m * NO + n]);
        float u = nu[((size_t)fv * M_ + m) * NO + n];
        float w = th * (u * 0.2f + 0.9f) * inv;
        sw[ml][nl] = w;
        sh[ml][nl] = d_gtilde[m * NO + n] * (w >= 0.f ? 1.f : -1.f);
    }
    __syncthreads();
    int nr = t >> 2, q = t & 3;
#pragma unroll
    for (int hf = 0; hf < 2; hf++) {
        float wv[8], hv[8];
#pragma unroll
        for (int j = 0; j < 8; j++) {
            wv[j] = sw[q * 16 + hf * 8 + j][nr];
            hv[j] = sh[q * 16 + hf * 8 + j][nr];
        }
        uint32_t hw[4], hb[4];
#pragma unroll
        for (int p = 0; p < 4; p++) {
            hw[p] = packh2(wv[2 * p + 1], wv[2 * p]);
            hb[p] = packh2(hv[2 * p + 1], hv[2 * p]);
        }
        size_t eoff = ((size_t)fv * NO + nt + nr) * NI + mt + q * 16 + hf * 8;
        *(uint4*)((char*)d_Bw + eoff * 2) = make_uint4(hw[0], hw[1], hw[2], hw[3]);
        *(uint4*)((char*)d_Hb + eoff * 2) = make_uint4(hb[0], hb[1], hb[2], hb[3]);
    }
}

// ---------------- A prep: fp16 + fused p1 partial ---------------------------------
__global__ void k_prepA(const float* __restrict__ a) {
    __shared__ float gs[NI];
    __shared__ float red[256];
    int t = threadIdx.x;
    int ec = blockIdx.x, fv = blockIdx.y;
    for (int i = t; i < NI; i += 256) gs[i] = d_gsumm[i];
    __syncthreads();
    size_t base = ((size_t)fv * E_ + ec * 128) * NI;
    const float* ab = a + base;
    float acc = 0.f;
    for (int j = 0; j < 64; j++) {
        int flat = j * 256 + t;
        int e = flat >> 7, c4 = flat & 127;
        size_t off = (size_t)e * NI + c4 * 4;
        float4 x = *(const float4*)(ab + off);
        acc += x.x * x.x * gs[c4 * 4 + 0] + x.y * x.y * gs[c4 * 4 + 1] +
               x.z * x.z * gs[c4 * 4 + 2] + x.w * x.w * gs[c4 * 4 + 3];
        uint32_t h0 = packh2(x.y, x.x);
        uint32_t h1 = packh2(x.w, x.z);
        *(uint2*)((char*)d_Ah + (base + off) * 2) = make_uint2(h0, h1);
    }
    red[t] = acc;
    __syncthreads();
    for (int s = 128; s > 0; s >>= 1) {
        if (t < s) red[t] += red[t + s];
        __syncthreads();
    }
    if (t == 0) d_p1p[fv * 16 + ec] = red[0];
}

// ---------------- main mma.sync GEMM ----------------------------------------------
// CTA 128(E) x 128(N); 8 warps = 2(m) x 4(n); warp 64x32; k-chunks of 32, 3 stages.
// stage = 3 matrices (A, W, H) x 128 rows x 80B = 30720B.
#define ROWB 80
#define MATB 10240
#define STAGEB 30720

__global__ void __launch_bounds__(256, 1)
k_gemm(float* __restrict__ out) {
    extern __shared__ __align__(16) char dsm[];
    uint32_t sb = smem_to_u32(dsm);
    int t = threadIdx.x;
    int wid = t >> 5, lane = t & 31;
    int wm = wid & 1, wn = wid >> 1;
    int fv = blockIdx.z, e0 = blockIdx.y * 128, n0 = blockIdx.x * 128;

    const char* gA = (const char*)d_Ah + ((size_t)fv * E_ + e0) * NI * 2;
    const char* gB = (const char*)d_Bw + ((size_t)fv * NO + n0) * NI * 2;
    const char* gH = (const char*)d_Hb + ((size_t)fv * NO + n0) * NI * 2;

    auto load_chunk = [&](int c, uint32_t base) {
#pragma unroll
        for (int it = 0; it < 2; it++) {
            int i = t + it * 256;
            int row = i >> 2, j = i & 3;
            uint32_t s = base + row * ROWB + j * 16;
            size_t g = (size_t)row * 1024 + (size_t)c * 64 + j * 16;
            cp_async16(s,            gA + g);
            cp_async16(s + MATB,     gB + g);
            cp_async16(s + 2 * MATB, gH + g);
        }
    };

    float zc[4][4][4], uc[4][4][4];
#pragma unroll
    for (int i = 0; i < 4; i++)
#pragma unroll
        for (int j = 0; j < 4; j++)
#pragma unroll
            for (int k = 0; k < 4; k++) { zc[i][j][k] = 0.f; uc[i][j][k] = 0.f; }

    uint32_t aoff = (wm * 64 + (lane & 15)) * ROWB + (lane >> 4) * 16;
    uint32_t boff = (wn * 32 + (lane & 15)) * ROWB + (lane >> 4) * 16;

    load_chunk(0, sb);          CP_COMMIT();
    load_chunk(1, sb + STAGEB); CP_COMMIT();

    for (int c = 0; c < 16; c++) {
        uint32_t base = sb + (uint32_t)(c % 3) * STAGEB;
        if (c < 15) { CP_WAIT1(); } else { CP_WAIT0(); }
        __syncthreads();
        if (c + 2 < 16) {
            load_chunk(c + 2, sb + (uint32_t)((c + 2) % 3) * STAGEB);
            CP_COMMIT();
        }
#pragma unroll
        for (int ks = 0; ks < 2; ks++) {
            uint32_t ah[4][4];
#pragma unroll
            for (int mt = 0; mt < 4; mt++) {
                uint32_t ad = base + aoff + mt * (16 * ROWB) + ks * 32;
                ldm4(ah[mt], ad);
            }
            uint32_t bw[2][4], hb[2][4];
#pragma unroll
            for (int pp = 0; pp < 2; pp++) {
                uint32_t bd = base + MATB + boff + pp * (16 * ROWB) + ks * 32;
                ldm4(bw[pp], bd);
                ldm4(hb[pp], bd + MATB);
            }
#pragma unroll
            for (int mt = 0; mt < 4; mt++)
#pragma unroll
                for (int nt = 0; nt < 4; nt++) {
                    int pp = nt >> 1, s = nt & 1;
                    mma_f16(zc[mt][nt], ah[mt], bw[pp][s], bw[pp][s + 2]);
                    mma_f16(uc[mt][nt], ah[mt], hb[pp][s], hb[pp][s + 2]);
                }
        }
    }

    // ---------------- epilogue ----------------
    float pw = 0.f;
    int lrow = lane >> 2, lcol = (lane & 3) * 2;
#pragma unroll
    for (int nt = 0; nt < 4; nt++) {
        int nc = n0 + wn * 32 + nt * 8 + lcol;
        float fz0 = d_fixz[fv * NO + nc],     fz1 = d_fixz[fv * NO + nc + 1];
        float fu0 = d_fixu[fv * NO + nc],     fu1 = d_fixu[fv * NO + nc + 1];
        float G0  = d_G[nc],                  G1  = d_G[nc + 1];
        float4 P0 = d_actp[nc],               P1  = d_actp[nc + 1];
#pragma unroll
        for (int mt = 0; mt < 4; mt++) {
            int r0 = e0 + wm * 64 + mt * 16 + lrow;
#pragma unroll
            for (int h = 0; h < 2; h++) {
                float z0 = zc[mt][nt][2 * h + 0] + fz0;
                float z1 = zc[mt][nt][2 * h + 1] + fz1;
                float u0 = uc[mt][nt][2 * h + 0] + fu0;
                float u1 = uc[mt][nt][2 * h + 1] + fu1;
                pw += z0 * (z0 * G0 - 2.f * u0);
                pw += z1 * (z1 * G1 - 2.f * u1);
                float2 o;
                o.x = P0.x + P0.y * tanhf((z0 - P0.z) * P0.w);
                o.y = P1.x + P1.y * tanhf((z1 - P1.z) * P1.w);
                *(float2*)(out + ((size_t)fv * E_ + r0 + h * 8) * NO + nc) = o;
            }
        }
    }

    __shared__ float red[256];
    red[t] = pw;
    __syncthreads();
    for (int s = 128; s > 0; s >>= 1) {
        if (t < s) red[t] += red[t + s];
        __syncthreads();
    }
    if (t == 0)
        d_pwp[(blockIdx.z * 4 + blockIdx.x) * 16 + blockIdx.y] = red[0];
}

// ---------------- final ----------------------------------------------------------
__global__ void k_final(float* __restrict__ out, int out_size) {
    __shared__ float red[256];
    int t = threadIdx.x;
    float s = 0.f;
    for (int i = t; i < 512; i += 256) s += d_pwp[i];
    for (int i = t; i < FV * 16; i += 256) s += d_p1p[i];
    red[t] = s;
    __syncthreads();
    for (int k = 128; k > 0; k >>= 1) {
        if (t < k) red[t] += red[t + k];
        __syncthreads();
    }
    if (t == 0) {
        float p1_ones = (float)(FV * E_) * d_gsumm[512];
        float power = (red[0] + p1_ones) / (float)(E_ * V_ * F_);
        long long total = (long long)FV * E_ * NO;
        if (out_size > total) out[total] = power;
    }
}

extern "C" void kernel_launch(void* const* d_in, const int* in_sizes, int n_in,
                              void* d_out, int out_size) {
    const float* a     = (const float*)d_in[0];
    const float* theta = (const float*)d_in[1];
    const float* coef  = (const float*)d_in[2];
    const float* nu    = (const float*)d_in[3];
    const float* gum   = (const float*)d_in[4];
    float* out = (float*)d_out;
    (void)in_sizes; (void)n_in;

    static int smem_set = 0;
    if (!smem_set) {
        cudaFuncSetAttribute(k_gemm, cudaFuncAttributeMaxDynamicSharedMemorySize,
                             3 * STAGEB);
        smem_set = 1;
    }

    k_gtilde<<<NO, 128>>>(theta);
    k_gsumm<<<M_, 128>>>();
    k_act<<<2, 256>>>(coef, gum);
    k_denp<<<dim3(32, FV), 512>>>(theta, nu);
    k_fix<<<FV, 512>>>(theta, nu);
    k_prepB<<<dim3(8, 8, FV), 256>>>(theta, nu);
    k_prepA<<<dim3(16, FV), 256>>>(a);
    k_gemm<<<dim3(4, 16, FV), 256, 3 * STAGEB>>>(out);
    k_final<<<1, 256>>>(out, out_size);
}

// round 7
// speedup vs baseline: 7.4253x; 1.2675x over previous
#include <cuda_runtime.h>
#include <cuda_fp16.h>
#include <math.h>
#include <stdint.h>

#define F_ 2
#define V_ 4
#define FV 8
#define E_ 2048
#define NI 512
#define NO 512
#define M_ 514
#define GMIN 0.01f
#define GMAX 10.0f
#define PGMIN 1e-4f

// ---------------- scratch ------------------------------------------------------
__device__ __align__(16) unsigned short d_Ah[FV * E_ * NI];   // x fp16 [fv][e][k]
__device__ __align__(16) unsigned short d_Bw[FV * NO * NI];   // W fp16 [fv][n][k]
__device__ __align__(16) unsigned short d_Hb[FV * NO * NI];   // H fp16 [fv][n][k]
__device__ float d_gtilde[M_ * NO];
__device__ float d_G[NO];
__device__ float d_gsumm[M_];
__device__ float d_denp[FV * 32 * NO];
__device__ float d_invden[FV * NO];
__device__ float d_fixz[FV * NO];
__device__ float d_fixu[FV * NO];
__device__ float4 d_actp[NO];
__device__ float d_p1p[FV * 64];
__device__ float d_pwp[512];

__constant__ float c_etas[16] = {
    0.05f, 0.90f, 0.20f, 8.0f,
    0.10f, 0.80f, 0.30f, 5.0f,
    0.00f, 1.00f, 0.25f, 10.0f,
    0.15f, 0.70f, 0.15f, 6.0f};

__device__ __forceinline__ float th_clip(float t) {
    return fminf(fmaxf(t, -GMAX), GMAX);
}
__device__ __forceinline__ float th_fwd(float t) {
    float c = th_clip(t);
    return (fabsf(c) < GMIN) ? 0.0f : c;
}

// ---------------- PTX helpers (base ISA only) -----------------------------------
__device__ __forceinline__ uint32_t smem_to_u32(const void* p) {
    uint32_t a;
    asm("{ .reg .u64 t; cvta.to.shared.u64 t, %1; cvt.u32.u64 %0, t; }" : "=r"(a) : "l"(p));
    return a;
}
__device__ __forceinline__ uint32_t packh2(float hi, float lo) {
    uint32_t r;
    asm("cvt.rn.f16x2.f32 %0, %1, %2;" : "=r"(r) : "f"(hi), "f"(lo));
    return r;
}
__device__ __forceinline__ void cp_async16(uint32_t s, const void* g) {
    asm volatile("cp.async.cg.shared.global [%0], [%1], 16;" :: "r"(s), "l"(g) : "memory");
}
#define CP_COMMIT() asm volatile("cp.async.commit_group;" ::: "memory")
#define CP_WAIT1()  asm volatile("cp.async.wait_group 1;" ::: "memory")
#define CP_WAIT0()  asm volatile("cp.async.wait_group 0;" ::: "memory")

__device__ __forceinline__ void ldm4(uint32_t r[4], uint32_t addr) {
    asm volatile("ldmatrix.sync.aligned.m8n8.x4.shared.b16 {%0,%1,%2,%3}, [%4];"
                 : "=r"(r[0]), "=r"(r[1]), "=r"(r[2]), "=r"(r[3]) : "r"(addr));
}
__device__ __forceinline__ void mma_f16(float c[4], const uint32_t a[4],
                                        uint32_t b0, uint32_t b1) {
    asm volatile(
        "mma.sync.aligned.m16n8k16.row.col.f32.f16.f16.f32 "
        "{%0,%1,%2,%3}, {%4,%5,%6,%7}, {%8,%9}, {%0,%1,%2,%3};"
        : "+f"(c[0]), "+f"(c[1]), "+f"(c[2]), "+f"(c[3])
        : "r"(a[0]), "r"(a[1]), "r"(a[2]), "r"(a[3]), "r"(b0), "r"(b1));
}

// ---------------- g_tilde, G (+ fused activation select) -------------------------
__global__ void k_gtilde(const float* __restrict__ theta,
                         const float* __restrict__ coef,
                         const float* __restrict__ gum) {
    int n = blockIdx.x;
    int t = threadIdx.x;
    __shared__ float red[128];
    float mn = 1e30f;
    for (int m = t; m < M_; m += 128)
        mn = fminf(mn, fabsf(th_clip(theta[m * NO + n])));
    red[t] = mn;
    __syncthreads();
    for (int s = 64; s > 0; s >>= 1) {
        if (t < s) red[t] = fminf(red[t], red[t + s]);
        __syncthreads();
    }
    float scale = PGMIN / red[0];
    __syncthreads();
    float sum = 0.f;
    for (int m = t; m < M_; m += 128) {
        float g = fabsf(th_clip(theta[m * NO + n])) * scale;
        d_gtilde[m * NO + n] = g;
        sum += g;
    }
    red[t] = sum;
    __syncthreads();
    for (int s = 64; s > 0; s >>= 1) {
        if (t < s) red[t] += red[t + s];
        __syncthreads();
    }
    if (t == 0) {
        d_G[n] = red[0];
        float best = -1e30f;
        int bi = 0;
#pragma unroll
        for (int i = 0; i < 4; i++) {
            float c = fminf(fmaxf(coef[i * NO + n], -1.f), 1.f);
            float g = gum[i * NO + n];
            float gn = -logf(-logf(g + 1e-20f) + 1e-20f);
            float v = c + gn;
            if (v > best) { best = v; bi = i; }
        }
        d_actp[n] = make_float4(c_etas[bi * 4 + 0], c_etas[bi * 4 + 1],
                                c_etas[bi * 4 + 2], c_etas[bi * 4 + 3]);
    }
}

__global__ void k_gsumm() {
    int m = blockIdx.x;
    int t = threadIdx.x;
    __shared__ float red[128];
    float s = 0.f;
    for (int n = t; n < NO; n += 128) s += d_gtilde[m * NO + n];
    red[t] = s;
    __syncthreads();
    for (int k = 64; k > 0; k >>= 1) {
        if (t < k) red[t] += red[t + k];
        __syncthreads();
    }
    if (t == 0) d_gsumm[m] = red[0];
}

// ---------------- denominator partials ------------------------------------------
__global__ void k_denp(const float* __restrict__ theta, const float* __restrict__ nu) {
    int n = blockIdx.y * 256 + threadIdx.x;
    int bx = blockIdx.x;
    int fv = blockIdx.z;
    int m0 = bx * 17, m1 = min(M_, m0 + 17);
    float acc = 0.f;
#pragma unroll 17
    for (int m = m0; m < m1; m++) {
        float t = th_fwd(theta[m * NO + n]);
        float u = nu[((size_t)fv * M_ + m) * NO + n];
        acc += fabsf(t * (u * 0.2f + 0.9f));
    }
    d_denp[((size_t)fv * 32 + bx) * NO + n] = acc;
}

// ---------------- invden + exact fp32 fix rows (m = 512) ------------------------
__global__ void k_fix(const float* __restrict__ theta, const float* __restrict__ nu) {
    int fv = blockIdx.x;
    int n = threadIdx.x;
    float den = 1e-10f;
#pragma unroll
    for (int i = 0; i < 32; i++) den += d_denp[((size_t)fv * 32 + i) * NO + n];
    float inv = 1.f / den;
    d_invden[fv * NO + n] = inv;
    float th = th_fwd(theta[512 * NO + n]);
    float u = nu[((size_t)fv * M_ + 512) * NO + n];
    float tn = th * (u * 0.2f + 0.9f);
    d_fixz[fv * NO + n] = tn * inv;
    d_fixu[fv * NO + n] = d_gtilde[512 * NO + n] * (tn >= 0.f ? 1.f : -1.f);
}

// ---------------- B prep: W + H fp16, transposed to [n][k] -----------------------
__global__ void k_prepB(const float* __restrict__ theta, const float* __restrict__ nu) {
    __shared__ float sw[64][65], sh[64][65];
    int t = threadIdx.x;
    int mt = blockIdx.x * 64, nt = blockIdx.y * 64, fv = blockIdx.z;
    int nl = t & 63;
    float inv = d_invden[fv * NO + nt + nl];
#pragma unroll 4
    for (int r = 0; r < 16; r++) {
        int ml = (t >> 6) * 16 + r;
        int m = mt + ml, n = nt + nl;
        float th = th_fwd(theta[m * NO + n]);
        float u = nu[((size_t)fv * M_ + m) * NO + n];
        float w = th * (u * 0.2f + 0.9f) * inv;
        sw[ml][nl] = w;
        sh[ml][nl] = d_gtilde[m * NO + n] * (w >= 0.f ? 1.f : -1.f);
    }
    __syncthreads();
    int nr = t >> 2, q = t & 3;
#pragma unroll
    for (int hf = 0; hf < 2; hf++) {
        float wv[8], hv[8];
#pragma unroll
        for (int j = 0; j < 8; j++) {
            wv[j] = sw[q * 16 + hf * 8 + j][nr];
            hv[j] = sh[q * 16 + hf * 8 + j][nr];
        }
        uint32_t hw[4], hb[4];
#pragma unroll
        for (int p = 0; p < 4; p++) {
            hw[p] = packh2(wv[2 * p + 1], wv[2 * p]);
            hb[p] = packh2(hv[2 * p + 1], hv[2 * p]);
        }
        size_t eoff = ((size_t)fv * NO + nt + nr) * NI + mt + q * 16 + hf * 8;
        *(uint4*)((char*)d_Bw + eoff * 2) = make_uint4(hw[0], hw[1], hw[2], hw[3]);
        *(uint4*)((char*)d_Hb + eoff * 2) = make_uint4(hb[0], hb[1], hb[2], hb[3]);
    }
}

// ---------------- A prep: fp16 + fused p1 partial ---------------------------------
__global__ void k_prepA(const float* __restrict__ a) {
    __shared__ float gs[NI];
    __shared__ float red[256];
    int t = threadIdx.x;
    int ec = blockIdx.x, fv = blockIdx.y;   // 64 chunks of 32 rows
    for (int i = t; i < NI; i += 256) gs[i] = d_gsumm[i];
    __syncthreads();
    size_t base = ((size_t)fv * E_ + ec * 32) * NI;
    const float* ab = a + base;
    float acc = 0.f;
#pragma unroll 4
    for (int j = 0; j < 16; j++) {
        int flat = j * 256 + t;
        int e = flat >> 7, c4 = flat & 127;
        size_t off = (size_t)e * NI + c4 * 4;
        float4 x = *(const float4*)(ab + off);
        acc += x.x * x.x * gs[c4 * 4 + 0] + x.y * x.y * gs[c4 * 4 + 1] +
               x.z * x.z * gs[c4 * 4 + 2] + x.w * x.w * gs[c4 * 4 + 3];
        uint32_t h0 = packh2(x.y, x.x);
        uint32_t h1 = packh2(x.w, x.z);
        *(uint2*)((char*)d_Ah + (base + off) * 2) = make_uint2(h0, h1);
    }
    red[t] = acc;
    __syncthreads();
    for (int s = 128; s > 0; s >>= 1) {
        if (t < s) red[t] += red[t + s];
        __syncthreads();
    }
    if (t == 0) d_p1p[fv * 64 + ec] = red[0];
}

// ---------------- main mma.sync GEMM ----------------------------------------------
// CTA 128(E) x 128(N); 16 warps = 4(m) x 4(n); warp 32x32; k-chunks of 32, 3 stages.
#define ROWB 80
#define MATB 10240
#define STAGEB 30720

__global__ void __launch_bounds__(512, 1)
k_gemm(float* __restrict__ out) {
    extern __shared__ __align__(16) char dsm[];
    uint32_t sb = smem_to_u32(dsm);
    int t = threadIdx.x;
    int wid = t >> 5, lane = t & 31;
    int wm = wid & 3, wn = wid >> 2;
    int fv = blockIdx.z, e0 = blockIdx.y * 128, n0 = blockIdx.x * 128;

    const char* gA = (const char*)d_Ah + ((size_t)fv * E_ + e0) * NI * 2;
    const char* gB = (const char*)d_Bw + ((size_t)fv * NO + n0) * NI * 2;
    const char* gH = (const char*)d_Hb + ((size_t)fv * NO + n0) * NI * 2;

    // 512 threads: one cp.async per matrix per thread per chunk
    int lrowc = t >> 2, lj = t & 3;
    auto load_chunk = [&](int c, uint32_t base) {
        uint32_t s = base + lrowc * ROWB + lj * 16;
        size_t g = (size_t)lrowc * 1024 + (size_t)c * 64 + lj * 16;
        cp_async16(s,            gA + g);
        cp_async16(s + MATB,     gB + g);
        cp_async16(s + 2 * MATB, gH + g);
    };

    float zc[2][4][4], uc[2][4][4];
#pragma unroll
    for (int i = 0; i < 2; i++)
#pragma unroll
        for (int j = 0; j < 4; j++)
#pragma unroll
            for (int k = 0; k < 4; k++) { zc[i][j][k] = 0.f; uc[i][j][k] = 0.f; }

    uint32_t aoff = (wm * 32 + (lane & 15)) * ROWB + (lane >> 4) * 16;
    uint32_t boff = (wn * 32 + (lane & 15)) * ROWB + (lane >> 4) * 16;

    load_chunk(0, sb);          CP_COMMIT();
    load_chunk(1, sb + STAGEB); CP_COMMIT();

    for (int c = 0; c < 16; c++) {
        uint32_t base = sb + (uint32_t)(c % 3) * STAGEB;
        if (c < 15) { CP_WAIT1(); } else { CP_WAIT0(); }
        __syncthreads();
        if (c + 2 < 16) {
            load_chunk(c + 2, sb + (uint32_t)((c + 2) % 3) * STAGEB);
            CP_COMMIT();
        }
#pragma unroll
        for (int ks = 0; ks < 2; ks++) {
            uint32_t ah[2][4];
#pragma unroll
            for (int mt = 0; mt < 2; mt++) {
                uint32_t ad = base + aoff + mt * (16 * ROWB) + ks * 32;
                ldm4(ah[mt], ad);
            }
            uint32_t bw[2][4], hb[2][4];
#pragma unroll
            for (int pp = 0; pp < 2; pp++) {
                uint32_t bd = base + MATB + boff + pp * (16 * ROWB) + ks * 32;
                ldm4(bw[pp], bd);
                ldm4(hb[pp], bd + MATB);
            }
#pragma unroll
            for (int mt = 0; mt < 2; mt++)
#pragma unroll
                for (int nt = 0; nt < 4; nt++) {
                    int pp = nt >> 1, s = nt & 1;
                    mma_f16(zc[mt][nt], ah[mt], bw[pp][s], bw[pp][s + 2]);
                    mma_f16(uc[mt][nt], ah[mt], hb[pp][s], hb[pp][s + 2]);
                }
        }
    }

    // ---------------- epilogue ----------------
    float pw = 0.f;
    int lrow = lane >> 2, lcol = (lane & 3) * 2;
#pragma unroll
    for (int nt = 0; nt < 4; nt++) {
        int nc = n0 + wn * 32 + nt * 8 + lcol;
        float fz0 = d_fixz[fv * NO + nc],     fz1 = d_fixz[fv * NO + nc + 1];
        float fu0 = d_fixu[fv * NO + nc],     fu1 = d_fixu[fv * NO + nc + 1];
        float G0  = d_G[nc],                  G1  = d_G[nc + 1];
        float4 P0 = d_actp[nc],               P1  = d_actp[nc + 1];
#pragma unroll
        for (int mt = 0; mt < 2; mt++) {
            int r0 = e0 + wm * 32 + mt * 16 + lrow;
#pragma unroll
            for (int h = 0; h < 2; h++) {
                float z0 = zc[mt][nt][2 * h + 0] + fz0;
                float z1 = zc[mt][nt][2 * h + 1] + fz1;
                float u0 = uc[mt][nt][2 * h + 0] + fu0;
                float u1 = uc[mt][nt][2 * h + 1] + fu1;
                pw += z0 * (z0 * G0 - 2.f * u0);
                pw += z1 * (z1 * G1 - 2.f * u1);
                float2 o;
                o.x = P0.x + P0.y * tanhf((z0 - P0.z) * P0.w);
                o.y = P1.x + P1.y * tanhf((z1 - P1.z) * P1.w);
                *(float2*)(out + ((size_t)fv * E_ + r0 + h * 8) * NO + nc) = o;
            }
        }
    }

    __shared__ float red[512];
    red[t] = pw;
    __syncthreads();
    for (int s = 256; s > 0; s >>= 1) {
        if (t < s) red[t] += red[t + s];
        __syncthreads();
    }
    if (t == 0)
        d_pwp[(blockIdx.z * 4 + blockIdx.x) * 16 + blockIdx.y] = red[0];
}

// ---------------- final ----------------------------------------------------------
__global__ void k_final(float* __restrict__ out, int out_size) {
    __shared__ float red[256];
    int t = threadIdx.x;
    float s = 0.f;
    for (int i = t; i < 512; i += 256) s += d_pwp[i];
    for (int i = t; i < FV * 64; i += 256) s += d_p1p[i];
    red[t] = s;
    __syncthreads();
    for (int k = 128; k > 0; k >>= 1) {
        if (t < k) red[t] += red[t + k];
        __syncthreads();
    }
    if (t == 0) {
        float p1_ones = (float)(FV * E_) * d_gsumm[512];
        float power = (red[0] + p1_ones) / (float)(E_ * V_ * F_);
        long long total = (long long)FV * E_ * NO;
        if (out_size > total) out[total] = power;
    }
}

extern "C" void kernel_launch(void* const* d_in, const int* in_sizes, int n_in,
                              void* d_out, int out_size) {
    const float* a     = (const float*)d_in[0];
    const float* theta = (const float*)d_in[1];
    const float* coef  = (const float*)d_in[2];
    const float* nu    = (const float*)d_in[3];
    const float* gum   = (const float*)d_in[4];
    float* out = (float*)d_out;
    (void)in_sizes; (void)n_in;

    static int smem_set = 0;
    if (!smem_set) {
        cudaFuncSetAttribute(k_gemm, cudaFuncAttributeMaxDynamicSharedMemorySize,
                             3 * STAGEB);
        smem_set = 1;
    }

    k_gtilde<<<NO, 128>>>(theta, coef, gum);
    k_gsumm<<<M_, 128>>>();
    k_denp<<<dim3(32, 2, FV), 256>>>(theta, nu);
    k_fix<<<FV, 512>>>(theta, nu);
    k_prepB<<<dim3(8, 8, FV), 256>>>(theta, nu);
    k_prepA<<<dim3(64, FV), 256>>>(a);
    k_gemm<<<dim3(4, 16, FV), 512, 3 * STAGEB>>>(out);
    k_final<<<1, 256>>>(out, out_size);
}